// round 6
// baseline (speedup 1.0000x reference)
#include <cuda_runtime.h>
#include <cuda_bf16.h>
#include <cstdint>
#include <cstddef>

constexpr int B_ = 4, S_ = 2048, H_ = 1024, NH_ = 16, HD_ = 64;
constexpr int M_ = B_ * S_;

constexpr float SCALE_Q = 0.18033688011112042f;  // 0.125 * log2(e)
// int8 quantization (symmetric construction -> shared correction scale)
constexpr float RA = 5.0f;        // activation clip range
constexpr float RW = 0.15625f;    // weight clip range (5 sigma, sigma=1/32)
constexpr float QA_H = 127.0f / RA;
constexpr float QA_L = 127.0f * 256.0f / RA;
constexpr float QW_H = 127.0f / RW;
constexpr float QW_L = 127.0f * 256.0f / RW;
constexpr float SCOR = (RA * RW / 256.0f) / (127.0f * 127.0f);

// Scratch
__device__ __nv_bfloat16 g_xhi[(size_t)M_ * H_];
__device__ int8_t        g_x8h[(size_t)M_ * H_];
__device__ int8_t        g_x8l[(size_t)M_ * H_];
__device__ __nv_bfloat16 g_whi[4 * (size_t)H_ * H_];
__device__ int8_t        g_w8h[4 * (size_t)H_ * H_];
__device__ int8_t        g_w8l[4 * (size_t)H_ * H_];
__device__ __nv_bfloat16 g_qhi[(size_t)M_ * H_];
__device__ __nv_bfloat16 g_qlo[(size_t)M_ * H_];
__device__ __nv_bfloat16 g_khi[(size_t)M_ * H_];
__device__ __nv_bfloat16 g_klo[(size_t)M_ * H_];
__device__ __nv_bfloat16 g_vhi[(size_t)M_ * H_];
__device__ __nv_bfloat16 g_vlo[(size_t)M_ * H_];
__device__ __nv_bfloat16 g_ahi[(size_t)M_ * H_];
__device__ int8_t        g_a8h[(size_t)M_ * H_];
__device__ int8_t        g_a8l[(size_t)M_ * H_];

__device__ __forceinline__ uint32_t smem_u32(const void* p) {
    uint32_t a;
    asm("{ .reg .u64 t; cvta.to.shared.u64 t, %1; cvt.u32.u64 %0, t; }"
        : "=r"(a) : "l"(p));
    return a;
}
__device__ __forceinline__ void cp_async16(uint32_t dst, const void* src) {
    asm volatile("cp.async.cg.shared.global [%0], [%1], 16;"
                 :: "r"(dst), "l"(src) : "memory");
}
#define CP_COMMIT() asm volatile("cp.async.commit_group;" ::: "memory")
#define CP_WAIT(n)  asm volatile("cp.async.wait_group %0;" :: "n"(n) : "memory")

__device__ __forceinline__ void ldmatrix_x4(uint32_t* r, uint32_t a) {
    asm volatile("ldmatrix.sync.aligned.m8n8.x4.shared.b16 {%0,%1,%2,%3}, [%4];"
                 : "=r"(r[0]), "=r"(r[1]), "=r"(r[2]), "=r"(r[3]) : "r"(a));
}
__device__ __forceinline__ void ldmatrix_x2(uint32_t* r, uint32_t a) {
    asm volatile("ldmatrix.sync.aligned.m8n8.x2.shared.b16 {%0,%1}, [%2];"
                 : "=r"(r[0]), "=r"(r[1]) : "r"(a));
}
__device__ __forceinline__ void ldmatrix_x2_trans(uint32_t* r, uint32_t a) {
    asm volatile("ldmatrix.sync.aligned.m8n8.x2.trans.shared.b16 {%0,%1}, [%2];"
                 : "=r"(r[0]), "=r"(r[1]) : "r"(a));
}
__device__ __forceinline__ void mma_bf16(float* c, const uint32_t* a,
                                         const uint32_t* b) {
    asm volatile(
        "mma.sync.aligned.m16n8k16.row.col.f32.bf16.bf16.f32 "
        "{%0,%1,%2,%3}, {%4,%5,%6,%7}, {%8,%9}, {%0,%1,%2,%3};"
        : "+f"(c[0]), "+f"(c[1]), "+f"(c[2]), "+f"(c[3])
        : "r"(a[0]), "r"(a[1]), "r"(a[2]), "r"(a[3]), "r"(b[0]), "r"(b[1]));
}
__device__ __forceinline__ void mma_s8(int* c, const uint32_t* a,
                                       const uint32_t* b) {
    asm volatile(
        "mma.sync.aligned.m16n8k32.row.col.s32.s8.s8.s32 "
        "{%0,%1,%2,%3}, {%4,%5,%6,%7}, {%8,%9}, {%0,%1,%2,%3};"
        : "+r"(c[0]), "+r"(c[1]), "+r"(c[2]), "+r"(c[3])
        : "r"(a[0]), "r"(a[1]), "r"(a[2]), "r"(a[3]), "r"(b[0]), "r"(b[1]));
}
__device__ __forceinline__ uint32_t lds32(uint32_t a) {
    uint32_t v;
    asm volatile("ld.shared.b32 %0, [%1];" : "=r"(v) : "r"(a));
    return v;
}
__device__ __forceinline__ float ex2f(float x) {
    float y; asm("ex2.approx.ftz.f32 %0, %1;" : "=f"(y) : "f"(x)); return y;
}
__device__ __forceinline__ float trunc_bf(float x) {
    return __uint_as_float(__float_as_uint(x) & 0xFFFF0000u);
}
__device__ __forceinline__ uint32_t prmt7632(uint32_t a, uint32_t b) {
    uint32_t d;
    asm("prmt.b32 %0, %1, %2, 0x7632;" : "=r"(d) : "r"(a), "r"(b));
    return d;
}
__device__ __forceinline__ uint32_t bf16x2_rn(float h, float l) {
    uint32_t d;
    asm("cvt.rn.satfinite.bf16x2.f32 %0, %1, %2;" : "=r"(d) : "f"(h), "f"(l));
    return d;
}
__device__ __forceinline__ int q8i(float x, float s) {
    int v = __float2int_rn(x * s);
    return max(-127, min(127, v));
}
__device__ __forceinline__ uint32_t pack4(int a, int b, int c, int d) {
    return (uint32_t)(a & 0xFF) | ((uint32_t)(b & 0xFF) << 8) |
           ((uint32_t)(c & 0xFF) << 16) | ((uint32_t)(d & 0xFF) << 24);
}
// bf16 rn of x, plus exact residual
__device__ __forceinline__ float bf_rn_res(float x, float& res) {
    uint32_t p = bf16x2_rn(0.f, x);          // low half = rn(x)
    float h = __uint_as_float(p << 16);
    res = x - h;
    return h;
}

// ---------------------------------------------------------------------------
// Split fp32 -> bf16(rn) hi + int8(full) + int8(residual)
// ---------------------------------------------------------------------------
template <bool ISW>
__global__ __launch_bounds__(256)
void split_kernel(const float* __restrict__ src, __nv_bfloat16* __restrict__ hi,
                  int8_t* __restrict__ o8h, int8_t* __restrict__ o8l, int n4)
{
    const float sh = ISW ? QW_H : QA_H;
    const float sl = ISW ? QW_L : QA_L;
    int i = blockIdx.x * blockDim.x + threadIdx.x;
    if (i >= n4) return;
    float4 v = reinterpret_cast<const float4*>(src)[i];
    float r0, r1, r2, r3;
    bf_rn_res(v.x, r0); bf_rn_res(v.y, r1);
    bf_rn_res(v.z, r2); bf_rn_res(v.w, r3);
    uint2 hu;
    hu.x = bf16x2_rn(v.y, v.x);
    hu.y = bf16x2_rn(v.w, v.z);
    reinterpret_cast<uint2*>(hi)[i] = hu;
    reinterpret_cast<uint32_t*>(o8h)[i] =
        pack4(q8i(v.x, sh), q8i(v.y, sh), q8i(v.z, sh), q8i(v.w, sh));
    reinterpret_cast<uint32_t*>(o8l)[i] =
        pack4(q8i(r0, sl), q8i(r1, sl), q8i(r2, sl), q8i(r3, sl));
}

// ---------------------------------------------------------------------------
// Hybrid GEMM: C = (A@W^T + bias)*scale.
// pass1 bf16 hi*hi; corrections a*w_lo + a_lo*w via int8 k32 IMMA (s32 acc
// persistent across K, folded once in epilogue).
// CTA 128x128, 8 warps (64x32), K-chunk 32, double buffered.
// MODE 0: fp32 out [M,H]. MODE 1: bf16 hi/lo scatter [B*NH,S,HD].
// ---------------------------------------------------------------------------
constexpr int RPB = 40, RP8 = 48;
constexpr int O_AB = 0, O_BB = 10240, O_A8H = 20480, O_A8L = 26624;
constexpr int O_B8H = 32768, O_B8L = 38912;
constexpr int GBUF = 45056;
constexpr int GEMM_SMEM = 2 * GBUF;

template <int MODE>
__global__ __launch_bounds__(256, 1)
void gemm_hyb(const __nv_bfloat16* __restrict__ Ahi,
              const int8_t* __restrict__ A8h, const int8_t* __restrict__ A8l,
              const __nv_bfloat16* __restrict__ Whi,
              const int8_t* __restrict__ W8h, const int8_t* __restrict__ W8l,
              const float* __restrict__ bias, float* __restrict__ Cf,
              __nv_bfloat16* __restrict__ Chi, __nv_bfloat16* __restrict__ Clo,
              float scale)
{
    extern __shared__ char smem[];
    const uint32_t sb = smem_u32(smem);
    const int tid = threadIdx.x, wid = tid >> 5, lane = tid & 31;
    const int m0 = blockIdx.y * 128, n0 = blockIdx.x * 128;
    const int wm = (wid & 1) * 64, wn = (wid >> 1) * 32;

    float facc[4][4][4];
    int   iacc[4][4][4];
    #pragma unroll
    for (int mi = 0; mi < 4; mi++)
        #pragma unroll
        for (int ni = 0; ni < 4; ni++)
            #pragma unroll
            for (int r = 0; r < 4; r++) { facc[mi][ni][r] = 0.f; iacc[mi][ni][r] = 0; }

    auto issue = [&](int c) {
        const int k0 = c * 32;
        const uint32_t bs = sb + (c & 1) * GBUF;
        #pragma unroll
        for (int t = 0; t < 2; t++) {
            int u = tid + t * 256, row = u >> 2, seg = u & 3;
            cp_async16(bs + O_AB + (row * RPB + seg * 8) * 2,
                       Ahi + (size_t)(m0 + row) * H_ + k0 + seg * 8);
            cp_async16(bs + O_BB + (row * RPB + seg * 8) * 2,
                       Whi + (size_t)(n0 + row) * H_ + k0 + seg * 8);
        }
        {
            int row = tid >> 1, seg = tid & 1;
            uint32_t d = row * RP8 + seg * 16;
            size_t ga = (size_t)(m0 + row) * H_ + k0 + seg * 16;
            size_t gb = (size_t)(n0 + row) * H_ + k0 + seg * 16;
            cp_async16(bs + O_A8H + d, A8h + ga);
            cp_async16(bs + O_A8L + d, A8l + ga);
            cp_async16(bs + O_B8H + d, W8h + gb);
            cp_async16(bs + O_B8L + d, W8l + gb);
        }
        CP_COMMIT();
    };

    issue(0);
    constexpr int NCH = H_ / 32;
    const int g = lane >> 2, t4 = (lane & 3) * 4;

    for (int c = 0; c < NCH; c++) {
        if (c + 1 < NCH) { issue(c + 1); CP_WAIT(1); }
        else             { CP_WAIT(0); }
        __syncthreads();
        const uint32_t bs = sb + (c & 1) * GBUF;

        // bf16 hi*hi
        #pragma unroll
        for (int ks = 0; ks < 2; ks++) {
            uint32_t af[4][4], bf[4][2];
            #pragma unroll
            for (int mi = 0; mi < 4; mi++)
                ldmatrix_x4(af[mi], bs + O_AB +
                    ((wm + mi * 16 + (lane & 15)) * RPB + ks * 16 + (lane >> 4) * 8) * 2);
            #pragma unroll
            for (int ni = 0; ni < 4; ni++) {
                int l = lane & 15;
                ldmatrix_x2(bf[ni], bs + O_BB +
                    ((wn + ni * 8 + (l & 7)) * RPB + ks * 16 + (l >> 3) * 8) * 2);
            }
            #pragma unroll
            for (int mi = 0; mi < 4; mi++)
                #pragma unroll
                for (int ni = 0; ni < 4; ni++)
                    mma_bf16(facc[mi][ni], af[mi], bf[ni]);
        }

        // int8 corrections (full k=32 per IMMA)
        {
            uint32_t a8h[4][4], a8l[4][4];
            #pragma unroll
            for (int mi = 0; mi < 4; mi++) {
                uint32_t r0 = bs + (wm + mi * 16 + g) * RP8 + t4;
                a8h[mi][0] = lds32(r0 + O_A8H);
                a8h[mi][1] = lds32(r0 + O_A8H + 8 * RP8);
                a8h[mi][2] = lds32(r0 + O_A8H + 16);
                a8h[mi][3] = lds32(r0 + O_A8H + 8 * RP8 + 16);
                a8l[mi][0] = lds32(r0 + O_A8L);
                a8l[mi][1] = lds32(r0 + O_A8L + 8 * RP8);
                a8l[mi][2] = lds32(r0 + O_A8L + 16);
                a8l[mi][3] = lds32(r0 + O_A8L + 8 * RP8 + 16);
            }
            #pragma unroll
            for (int ni = 0; ni < 4; ni++) {
                uint32_t rb = bs + (wn + ni * 8 + g) * RP8 + t4;
                uint32_t b8h[2], b8l[2];
                b8h[0] = lds32(rb + O_B8H); b8h[1] = lds32(rb + O_B8H + 16);
                b8l[0] = lds32(rb + O_B8L); b8l[1] = lds32(rb + O_B8L + 16);
                #pragma unroll
                for (int mi = 0; mi < 4; mi++) {
                    mma_s8(iacc[mi][ni], a8h[mi], b8l);
                    mma_s8(iacc[mi][ni], a8l[mi], b8h);
                }
            }
        }
        __syncthreads();
    }

    const int frow = lane >> 2, fcol = (lane & 3) * 2;
    #pragma unroll
    for (int mi = 0; mi < 4; mi++) {
        #pragma unroll
        for (int ni = 0; ni < 4; ni++) {
            const int n = n0 + wn + ni * 8 + fcol;
            const float b0 = __ldg(&bias[n]);
            const float b1 = __ldg(&bias[n + 1]);
            #pragma unroll
            for (int half = 0; half < 2; half++) {
                const int m = m0 + wm + mi * 16 + frow + half * 8;
                float vx = (facc[mi][ni][half*2+0] + SCOR * (float)iacc[mi][ni][half*2+0] + b0) * scale;
                float vy = (facc[mi][ni][half*2+1] + SCOR * (float)iacc[mi][ni][half*2+1] + b1) * scale;
                if (MODE == 0) {
                    float2 val{vx, vy};
                    *reinterpret_cast<float2*>(&Cf[(size_t)m * H_ + n]) = val;
                } else {
                    const int b = m >> 11, s = m & 2047;
                    const int h = n >> 6, hd = n & 63;
                    size_t idx = (((size_t)(b * NH_ + h)) * S_ + s) * HD_ + hd;
                    uint32_t hi = prmt7632(__float_as_uint(vx), __float_as_uint(vy));
                    uint32_t lo = bf16x2_rn(vy - trunc_bf(vy), vx - trunc_bf(vx));
                    reinterpret_cast<uint32_t*>(Chi)[idx >> 1] = hi;
                    reinterpret_cast<uint32_t*>(Clo)[idx >> 1] = lo;
                }
            }
        }
    }
}

// ---------------------------------------------------------------------------
// Flash attention (bf16x3, base-2 softmax) — unchanged compute; epilogue also
// emits int8 hi/lo for the O-projection.
// ---------------------------------------------------------------------------
constexpr int RP = 72, TSZ = 64 * RP * 2, KVOFF = 2 * TSZ;
constexpr int ATTN_SMEM = 2 * TSZ + 2 * 4 * TSZ;

__global__ __launch_bounds__(128)
void attn_mma(const __nv_bfloat16* __restrict__ qhi, const __nv_bfloat16* __restrict__ qlo,
              const __nv_bfloat16* __restrict__ khi, const __nv_bfloat16* __restrict__ klo,
              const __nv_bfloat16* __restrict__ vhi, const __nv_bfloat16* __restrict__ vlo,
              __nv_bfloat16* __restrict__ ahi, int8_t* __restrict__ a8h,
              int8_t* __restrict__ a8l)
{
    extern __shared__ char smem[];
    const uint32_t sb = smem_u32(smem);
    const int tid = threadIdx.x, wid = tid >> 5, lane = tid & 31;
    const int qt = 31 - blockIdx.x;
    const int bh = blockIdx.y;
    const int q0 = qt * 64;
    const size_t boff = (size_t)bh * S_ * HD_;
    const int wm = wid * 16;

    auto cp_tile = [&](uint32_t dst, const __nv_bfloat16* src) {
        #pragma unroll
        for (int t = 0; t < 4; t++) {
            int u = tid + t * 128, r = u >> 3, ch = u & 7;
            cp_async16(dst + (r * RP + ch * 8) * 2, src + (size_t)r * HD_ + ch * 8);
        }
    };
    cp_tile(sb,       qhi + boff + (size_t)q0 * HD_);
    cp_tile(sb + TSZ, qlo + boff + (size_t)q0 * HD_);
    CP_COMMIT();
    auto issue = [&](int kt) {
        uint32_t kb = sb + KVOFF + (kt & 1) * 4 * TSZ;
        const size_t o = boff + (size_t)kt * 64 * HD_;
        cp_tile(kb, khi + o);          cp_tile(kb + TSZ, klo + o);
        cp_tile(kb + 2 * TSZ, vhi + o); cp_tile(kb + 3 * TSZ, vlo + o);
        CP_COMMIT();
    };
    issue(0);
    CP_WAIT(1);
    __syncthreads();

    uint32_t qh[4][4], ql[4][4];
    #pragma unroll
    for (int ks = 0; ks < 4; ks++) {
        uint32_t a = sb + ((wm + (lane & 15)) * RP + ks * 16 + (lane >> 4) * 8) * 2;
        ldmatrix_x4(qh[ks], a);
        ldmatrix_x4(ql[ks], a + TSZ);
    }

    float o[8][4];
    #pragma unroll
    for (int j = 0; j < 8; j++)
        #pragma unroll
        for (int r = 0; r < 4; r++) o[j][r] = 0.f;
    float m_i[2] = {-1e30f, -1e30f}, l_i[2] = {0.f, 0.f};

    for (int kt = 0; kt <= qt; kt++) {
        if (kt < qt) { issue(kt + 1); CP_WAIT(1); }
        else         { CP_WAIT(0); }
        __syncthreads();
        const uint32_t kb = sb + KVOFF + (kt & 1) * 4 * TSZ;

        float s[8][4];
        #pragma unroll
        for (int j = 0; j < 8; j++)
            #pragma unroll
            for (int r = 0; r < 4; r++) s[j][r] = 0.f;

        #pragma unroll
        for (int ks = 0; ks < 4; ks++) {
            #pragma unroll
            for (int j = 0; j < 8; j++) {
                uint32_t bh2[2], bl2[2];
                int l = lane & 15;
                uint32_t ka = kb + ((8 * j + (l & 7)) * RP + ks * 16 + (l >> 3) * 8) * 2;
                ldmatrix_x2(bh2, ka);
                ldmatrix_x2(bl2, ka + TSZ);
                mma_bf16(s[j], qh[ks], bh2);
                mma_bf16(s[j], ql[ks], bh2);
                mma_bf16(s[j], qh[ks], bl2);
            }
        }

        if (kt == qt) {
            const int r0 = wm + (lane >> 2);
            #pragma unroll
            for (int j = 0; j < 8; j++) {
                const int kc = 8 * j + 2 * (lane & 3);
                if (kc     > r0)     s[j][0] = -1e30f;
                if (kc + 1 > r0)     s[j][1] = -1e30f;
                if (kc     > r0 + 8) s[j][2] = -1e30f;
                if (kc + 1 > r0 + 8) s[j][3] = -1e30f;
            }
        }

        float mx0 = -1e30f, mx1 = -1e30f;
        #pragma unroll
        for (int j = 0; j < 8; j++) {
            mx0 = fmaxf(mx0, fmaxf(s[j][0], s[j][1]));
            mx1 = fmaxf(mx1, fmaxf(s[j][2], s[j][3]));
        }
        mx0 = fmaxf(mx0, __shfl_xor_sync(~0u, mx0, 1));
        mx0 = fmaxf(mx0, __shfl_xor_sync(~0u, mx0, 2));
        mx1 = fmaxf(mx1, __shfl_xor_sync(~0u, mx1, 1));
        mx1 = fmaxf(mx1, __shfl_xor_sync(~0u, mx1, 2));
        const float nm0 = fmaxf(m_i[0], mx0), nm1 = fmaxf(m_i[1], mx1);
        const float c0 = ex2f(m_i[0] - nm0), c1 = ex2f(m_i[1] - nm1);
        m_i[0] = nm0; m_i[1] = nm1;

        float rs0 = 0.f, rs1 = 0.f;
        #pragma unroll
        for (int j = 0; j < 8; j++) {
            s[j][0] = ex2f(s[j][0] - nm0);
            s[j][1] = ex2f(s[j][1] - nm0);
            s[j][2] = ex2f(s[j][2] - nm1);
            s[j][3] = ex2f(s[j][3] - nm1);
            rs0 += s[j][0] + s[j][1];
            rs1 += s[j][2] + s[j][3];
        }
        rs0 += __shfl_xor_sync(~0u, rs0, 1);
        rs0 += __shfl_xor_sync(~0u, rs0, 2);
        rs1 += __shfl_xor_sync(~0u, rs1, 1);
        rs1 += __shfl_xor_sync(~0u, rs1, 2);
        l_i[0] = l_i[0] * c0 + rs0;
        l_i[1] = l_i[1] * c1 + rs1;
        #pragma unroll
        for (int j = 0; j < 8; j++) {
            o[j][0] *= c0; o[j][1] *= c0;
            o[j][2] *= c1; o[j][3] *= c1;
        }

        uint32_t ph[4][4], pl[4][4];
        #pragma unroll
        for (int k2 = 0; k2 < 4; k2++) {
            #pragma unroll
            for (int half = 0; half < 2; half++) {
                const int j = 2 * k2 + half;
                ph[k2][half*2+0] = prmt7632(__float_as_uint(s[j][0]), __float_as_uint(s[j][1]));
                ph[k2][half*2+1] = prmt7632(__float_as_uint(s[j][2]), __float_as_uint(s[j][3]));
                pl[k2][half*2+0] = bf16x2_rn(s[j][1] - trunc_bf(s[j][1]),
                                             s[j][0] - trunc_bf(s[j][0]));
                pl[k2][half*2+1] = bf16x2_rn(s[j][3] - trunc_bf(s[j][3]),
                                             s[j][2] - trunc_bf(s[j][2]));
            }
        }

        const uint32_t vb = kb + 2 * TSZ;
        #pragma unroll
        for (int k2 = 0; k2 < 4; k2++) {
            #pragma unroll
            for (int j = 0; j < 8; j++) {
                uint32_t vh2[2], vl2[2];
                uint32_t va = vb + ((k2 * 16 + (lane & 15)) * RP + 8 * j) * 2;
                ldmatrix_x2_trans(vh2, va);
                ldmatrix_x2_trans(vl2, va + TSZ);
                mma_bf16(o[j], ph[k2], vh2);
                mma_bf16(o[j], pl[k2], vh2);
                mma_bf16(o[j], ph[k2], vl2);
            }
        }
        __syncthreads();
    }

    // epilogue: bf16 rn hi + int8 hi/lo for O-projection
    const float inv0 = 1.f / l_i[0], inv1 = 1.f / l_i[1];
    const int b = bh >> 4, h = bh & 15;
    const int r0 = q0 + wm + (lane >> 2);
    const size_t base0 = ((size_t)(b * S_) + r0) * H_ + h * 64;
    const size_t base1 = base0 + (size_t)8 * H_;
    #pragma unroll
    for (int j = 0; j < 8; j++) {
        const int c = 8 * j + 2 * (lane & 3);
        float f[4] = {o[j][0]*inv0, o[j][1]*inv0, o[j][2]*inv1, o[j][3]*inv1};
        #pragma unroll
        for (int half = 0; half < 2; half++) {
            size_t base = half ? base1 : base0;
            float r0f, r1f;
            float h0 = bf_rn_res(f[half*2+0], r0f);
            float h1 = bf_rn_res(f[half*2+1], r1f);
            (void)h0; (void)h1;
            reinterpret_cast<uint32_t*>(ahi)[(base + c) >> 1] =
                bf16x2_rn(f[half*2+1], f[half*2+0]);
            uint16_t vh = (uint16_t)((q8i(f[half*2+0], QA_H) & 0xFF) |
                                     ((q8i(f[half*2+1], QA_H) & 0xFF) << 8));
            uint16_t vl = (uint16_t)((q8i(r0f, QA_L) & 0xFF) |
                                     ((q8i(r1f, QA_L) & 0xFF) << 8));
            *reinterpret_cast<uint16_t*>(&a8h[base + c]) = vh;
            *reinterpret_cast<uint16_t*>(&a8l[base + c]) = vl;
        }
    }
}

// ---------------------------------------------------------------------------
extern "C" void kernel_launch(void* const* d_in, const int* in_sizes, int n_in,
                              void* d_out, int out_size)
{
    const float* x  = (const float*)d_in[0];
    const float* Wq = (const float*)d_in[1];
    const float* bq = (const float*)d_in[2];
    const float* Wk = (const float*)d_in[3];
    const float* bk = (const float*)d_in[4];
    const float* Wv = (const float*)d_in[5];
    const float* bv = (const float*)d_in[6];
    const float* Wo = (const float*)d_in[7];
    const float* bo = (const float*)d_in[8];
    float* out = (float*)d_out;

    __nv_bfloat16 *xhi, *whi, *q_hi, *q_lo, *k_hi, *k_lo, *v_hi, *v_lo, *a_hi;
    int8_t *x8h, *x8l, *w8h, *w8l, *a8h, *a8l;
    cudaGetSymbolAddress((void**)&xhi, g_xhi);
    cudaGetSymbolAddress((void**)&x8h, g_x8h);
    cudaGetSymbolAddress((void**)&x8l, g_x8l);
    cudaGetSymbolAddress((void**)&whi, g_whi);
    cudaGetSymbolAddress((void**)&w8h, g_w8h);
    cudaGetSymbolAddress((void**)&w8l, g_w8l);
    cudaGetSymbolAddress((void**)&q_hi, g_qhi);
    cudaGetSymbolAddress((void**)&q_lo, g_qlo);
    cudaGetSymbolAddress((void**)&k_hi, g_khi);
    cudaGetSymbolAddress((void**)&k_lo, g_klo);
    cudaGetSymbolAddress((void**)&v_hi, g_vhi);
    cudaGetSymbolAddress((void**)&v_lo, g_vlo);
    cudaGetSymbolAddress((void**)&a_hi, g_ahi);
    cudaGetSymbolAddress((void**)&a8h, g_a8h);
    cudaGetSymbolAddress((void**)&a8l, g_a8l);

    cudaFuncSetAttribute(gemm_hyb<0>, cudaFuncAttributeMaxDynamicSharedMemorySize, GEMM_SMEM);
    cudaFuncSetAttribute(gemm_hyb<1>, cudaFuncAttributeMaxDynamicSharedMemorySize, GEMM_SMEM);
    cudaFuncSetAttribute(attn_mma, cudaFuncAttributeMaxDynamicSharedMemorySize, ATTN_SMEM);

    const size_t WN = (size_t)H_ * H_;
    {
        int n4 = (M_ * H_) / 4;
        split_kernel<false><<<(n4 + 255) / 256, 256>>>(x, xhi, x8h, x8l, n4);
        int w4 = (H_ * H_) / 4;
        split_kernel<true><<<(w4 + 255) / 256, 256>>>(Wq, whi + 0*WN, w8h + 0*WN, w8l + 0*WN, w4);
        split_kernel<true><<<(w4 + 255) / 256, 256>>>(Wk, whi + 1*WN, w8h + 1*WN, w8l + 1*WN, w4);
        split_kernel<true><<<(w4 + 255) / 256, 256>>>(Wv, whi + 2*WN, w8h + 2*WN, w8l + 2*WN, w4);
        split_kernel<true><<<(w4 + 255) / 256, 256>>>(Wo, whi + 3*WN, w8h + 3*WN, w8l + 3*WN, w4);
    }

    dim3 gg(H_ / 128, M_ / 128);
    gemm_hyb<1><<<gg, 256, GEMM_SMEM>>>(xhi, x8h, x8l, whi + 0*WN, w8h + 0*WN, w8l + 0*WN,
                                        bq, nullptr, q_hi, q_lo, SCALE_Q);
    gemm_hyb<1><<<gg, 256, GEMM_SMEM>>>(xhi, x8h, x8l, whi + 1*WN, w8h + 1*WN, w8l + 1*WN,
                                        bk, nullptr, k_hi, k_lo, 1.0f);
    gemm_hyb<1><<<gg, 256, GEMM_SMEM>>>(xhi, x8h, x8l, whi + 2*WN, w8h + 2*WN, w8l + 2*WN,
                                        bv, nullptr, v_hi, v_lo, 1.0f);

    dim3 ag(S_ / 64, B_ * NH_);
    attn_mma<<<ag, 128, ATTN_SMEM>>>(q_hi, q_lo, k_hi, k_lo, v_hi, v_lo,
                                     a_hi, a8h, a8l);

    gemm_hyb<0><<<gg, 256, GEMM_SMEM>>>(a_hi, a8h, a8l, whi + 3*WN, w8h + 3*WN, w8l + 3*WN,
                                        bo, out, nullptr, nullptr, 1.0f);
}

// round 7
// speedup vs baseline: 1.8692x; 1.8692x over previous
#include <cuda_runtime.h>
#include <cuda_bf16.h>
#include <cstdint>
#include <cstddef>

constexpr int B_ = 4, S_ = 2048, H_ = 1024, NH_ = 16, HD_ = 64;
constexpr int M_ = B_ * S_;
constexpr float SCALE_Q = 0.18033688011112042f;  // 0.125 * log2(e)

// Scratch (device globals)
__device__ __nv_bfloat16 g_xhi[(size_t)M_ * H_];
__device__ __nv_bfloat16 g_xlo[(size_t)M_ * H_];
__device__ __nv_bfloat16 g_whi[4 * (size_t)H_ * H_];
__device__ __nv_bfloat16 g_wlo[4 * (size_t)H_ * H_];
__device__ __nv_bfloat16 g_qhi[(size_t)M_ * H_];
__device__ __nv_bfloat16 g_qlo[(size_t)M_ * H_];
__device__ __nv_bfloat16 g_khi[(size_t)M_ * H_];
__device__ __nv_bfloat16 g_klo[(size_t)M_ * H_];
__device__ __nv_bfloat16 g_vhi[(size_t)M_ * H_];
__device__ __nv_bfloat16 g_vlo[(size_t)M_ * H_];
__device__ __nv_bfloat16 g_ahi[(size_t)M_ * H_];
__device__ __nv_bfloat16 g_alo[(size_t)M_ * H_];

__device__ __forceinline__ uint32_t smem_u32(const void* p) {
    uint32_t a;
    asm("{ .reg .u64 t; cvta.to.shared.u64 t, %1; cvt.u32.u64 %0, t; }"
        : "=r"(a) : "l"(p));
    return a;
}
__device__ __forceinline__ void cp_async16(uint32_t dst, const void* src) {
    asm volatile("cp.async.cg.shared.global [%0], [%1], 16;"
                 :: "r"(dst), "l"(src) : "memory");
}
#define CP_COMMIT() asm volatile("cp.async.commit_group;" ::: "memory")
#define CP_WAIT(n)  asm volatile("cp.async.wait_group %0;" :: "n"(n) : "memory")

__device__ __forceinline__ void ldmatrix_x4(uint32_t* r, uint32_t a) {
    asm volatile("ldmatrix.sync.aligned.m8n8.x4.shared.b16 {%0,%1,%2,%3}, [%4];"
                 : "=r"(r[0]), "=r"(r[1]), "=r"(r[2]), "=r"(r[3]) : "r"(a));
}
__device__ __forceinline__ void ldmatrix_x2(uint32_t* r, uint32_t a) {
    asm volatile("ldmatrix.sync.aligned.m8n8.x2.shared.b16 {%0,%1}, [%2];"
                 : "=r"(r[0]), "=r"(r[1]) : "r"(a));
}
__device__ __forceinline__ void ldmatrix_x2_trans(uint32_t* r, uint32_t a) {
    asm volatile("ldmatrix.sync.aligned.m8n8.x2.trans.shared.b16 {%0,%1}, [%2];"
                 : "=r"(r[0]), "=r"(r[1]) : "r"(a));
}
__device__ __forceinline__ void mma_bf16(float* c, const uint32_t* a,
                                         const uint32_t* b) {
    asm volatile(
        "mma.sync.aligned.m16n8k16.row.col.f32.bf16.bf16.f32 "
        "{%0,%1,%2,%3}, {%4,%5,%6,%7}, {%8,%9}, {%0,%1,%2,%3};"
        : "+f"(c[0]), "+f"(c[1]), "+f"(c[2]), "+f"(c[3])
        : "r"(a[0]), "r"(a[1]), "r"(a[2]), "r"(a[3]), "r"(b[0]), "r"(b[1]));
}
__device__ __forceinline__ float ex2f(float x) {
    float y; asm("ex2.approx.ftz.f32 %0, %1;" : "=f"(y) : "f"(x)); return y;
}
__device__ __forceinline__ float trunc_bf(float x) {
    return __uint_as_float(__float_as_uint(x) & 0xFFFF0000u);
}
__device__ __forceinline__ uint32_t prmt7632(uint32_t a, uint32_t b) {
    uint32_t d;
    asm("prmt.b32 %0, %1, %2, 0x7632;" : "=r"(d) : "r"(a), "r"(b));
    return d;
}
__device__ __forceinline__ uint32_t bf16x2_rn(float h, float l) {
    uint32_t d;
    asm("cvt.rn.satfinite.bf16x2.f32 %0, %1, %2;" : "=r"(d) : "f"(h), "f"(l));
    return d;
}

// ---------------------------------------------------------------------------
// Splits: fp32 -> bf16 hi (trunc) / bf16 lo (residual)
// ---------------------------------------------------------------------------
__global__ __launch_bounds__(256)
void split_x(const float* __restrict__ src, __nv_bfloat16* __restrict__ hi,
             __nv_bfloat16* __restrict__ lo, int n4)
{
    int i = blockIdx.x * blockDim.x + threadIdx.x;
    if (i >= n4) return;
    float4 v = reinterpret_cast<const float4*>(src)[i];
    float t0 = trunc_bf(v.x), t1 = trunc_bf(v.y), t2 = trunc_bf(v.z), t3 = trunc_bf(v.w);
    uint2 hu, lu;
    hu.x = prmt7632(__float_as_uint(v.x), __float_as_uint(v.y));
    hu.y = prmt7632(__float_as_uint(v.z), __float_as_uint(v.w));
    lu.x = bf16x2_rn(v.y - t1, v.x - t0);
    lu.y = bf16x2_rn(v.w - t3, v.z - t2);
    reinterpret_cast<uint2*>(hi)[i] = hu;
    reinterpret_cast<uint2*>(lo)[i] = lu;
}

struct WSplit { const float* src[4]; };

__global__ __launch_bounds__(256)
void split_w(WSplit ws, __nv_bfloat16* __restrict__ hiBase,
             __nv_bfloat16* __restrict__ loBase, int n4)
{
    const int w = blockIdx.y;
    const float* src = ws.src[w];
    __nv_bfloat16* hi = hiBase + (size_t)w * H_ * H_;
    __nv_bfloat16* lo = loBase + (size_t)w * H_ * H_;
    int i = blockIdx.x * blockDim.x + threadIdx.x;
    if (i >= n4) return;
    float4 v = reinterpret_cast<const float4*>(src)[i];
    float t0 = trunc_bf(v.x), t1 = trunc_bf(v.y), t2 = trunc_bf(v.z), t3 = trunc_bf(v.w);
    uint2 hu, lu;
    hu.x = prmt7632(__float_as_uint(v.x), __float_as_uint(v.y));
    hu.y = prmt7632(__float_as_uint(v.z), __float_as_uint(v.w));
    lu.x = bf16x2_rn(v.y - t1, v.x - t0);
    lu.y = bf16x2_rn(v.w - t3, v.z - t2);
    reinterpret_cast<uint2*>(hi)[i] = hu;
    reinterpret_cast<uint2*>(lo)[i] = lu;
}

// ---------------------------------------------------------------------------
// bf16x3 GEMM, pass-INTERLEAVED per K-chunk: C = (A@W^T + bias)*scale
// CTA 128x128, K-chunk 32 (load A_hi/A_lo/W_hi/W_lo once, do hh+hl+lh).
// MODE 1: fused QKV (blockIdx.z = weight), bf16 hi/lo scatter [B*NH,S,HD].
// MODE 0: fp32 out [M,H].
// ---------------------------------------------------------------------------
constexpr int RPB = 40;
constexpr int TB  = 128 * RPB * 2;     // 10240 per tile
constexpr int O_AH = 0, O_AL = TB, O_WH = 2 * TB, O_WL = 3 * TB;
constexpr int GBUF = 4 * TB;           // 40960
constexpr int GEMM_SMEM = 2 * GBUF;    // 81920

struct G3 {
    const float* bias[3];
    __nv_bfloat16* ohi[3];
    __nv_bfloat16* olo[3];
    float scale[3];
};

template <int MODE>
__global__ __launch_bounds__(256)
void gemm3(const __nv_bfloat16* __restrict__ Ahi,
           const __nv_bfloat16* __restrict__ Alo,
           const __nv_bfloat16* __restrict__ WhiB,
           const __nv_bfloat16* __restrict__ WloB,
           G3 g, float* __restrict__ Cf)
{
    extern __shared__ char smem[];
    const uint32_t sb = smem_u32(smem);
    const int tid = threadIdx.x, wid = tid >> 5, lane = tid & 31;
    const int z = (MODE == 1) ? blockIdx.z : 0;
    const int m0 = blockIdx.y * 128, n0 = blockIdx.x * 128;
    const int wm = (wid & 1) * 64, wn = (wid >> 1) * 32;
    const size_t WN = (size_t)H_ * H_;
    const __nv_bfloat16* Whi = WhiB + (size_t)z * WN;
    const __nv_bfloat16* Wlo = WloB + (size_t)z * WN;

    float acc[4][4][4];
    #pragma unroll
    for (int mi = 0; mi < 4; mi++)
        #pragma unroll
        for (int ni = 0; ni < 4; ni++)
            #pragma unroll
            for (int r = 0; r < 4; r++) acc[mi][ni][r] = 0.f;

    auto issue = [&](int c) {
        const int k0 = c * 32;
        const uint32_t bs = sb + (c & 1) * GBUF;
        #pragma unroll
        for (int t = 0; t < 2; t++) {
            int u = tid + t * 256;          // 0..511
            int row = u >> 2, seg = u & 3;  // 4 x 16B segs = 32 bf16
            uint32_t d = (row * RPB + seg * 8) * 2;
            size_t ga = (size_t)(m0 + row) * H_ + k0 + seg * 8;
            size_t gw = (size_t)(n0 + row) * H_ + k0 + seg * 8;
            cp_async16(bs + O_AH + d, Ahi + ga);
            cp_async16(bs + O_AL + d, Alo + ga);
            cp_async16(bs + O_WH + d, Whi + gw);
            cp_async16(bs + O_WL + d, Wlo + gw);
        }
        CP_COMMIT();
    };

    issue(0);
    constexpr int NCH = H_ / 32;   // 32

    for (int c = 0; c < NCH; c++) {
        if (c + 1 < NCH) { issue(c + 1); CP_WAIT(1); }
        else             { CP_WAIT(0); }
        __syncthreads();
        const uint32_t bs = sb + (c & 1) * GBUF;

        #pragma unroll
        for (int ks = 0; ks < 2; ks++) {
            const int l = lane & 15;
            uint32_t ah[4][4], bh[4][2];
            #pragma unroll
            for (int mi = 0; mi < 4; mi++)
                ldmatrix_x4(ah[mi], bs + O_AH +
                    ((wm + mi * 16 + l) * RPB + ks * 16 + (lane >> 4) * 8) * 2);
            #pragma unroll
            for (int ni = 0; ni < 4; ni++)
                ldmatrix_x2(bh[ni], bs + O_WH +
                    ((wn + ni * 8 + (l & 7)) * RPB + ks * 16 + (l >> 3) * 8) * 2);
            #pragma unroll
            for (int mi = 0; mi < 4; mi++)
                #pragma unroll
                for (int ni = 0; ni < 4; ni++)
                    mma_bf16(acc[mi][ni], ah[mi], bh[ni]);

            uint32_t bl[4][2];
            #pragma unroll
            for (int ni = 0; ni < 4; ni++)
                ldmatrix_x2(bl[ni], bs + O_WL +
                    ((wn + ni * 8 + (l & 7)) * RPB + ks * 16 + (l >> 3) * 8) * 2);
            #pragma unroll
            for (int mi = 0; mi < 4; mi++)
                #pragma unroll
                for (int ni = 0; ni < 4; ni++)
                    mma_bf16(acc[mi][ni], ah[mi], bl[ni]);

            uint32_t al[4][4];
            #pragma unroll
            for (int mi = 0; mi < 4; mi++)
                ldmatrix_x4(al[mi], bs + O_AL +
                    ((wm + mi * 16 + l) * RPB + ks * 16 + (lane >> 4) * 8) * 2);
            #pragma unroll
            for (int mi = 0; mi < 4; mi++)
                #pragma unroll
                for (int ni = 0; ni < 4; ni++)
                    mma_bf16(acc[mi][ni], al[mi], bh[ni]);
        }
        __syncthreads();
    }

    const float scale = g.scale[z];
    const float* bias = g.bias[z];
    const int frow = lane >> 2, fcol = (lane & 3) * 2;
    #pragma unroll
    for (int mi = 0; mi < 4; mi++) {
        #pragma unroll
        for (int ni = 0; ni < 4; ni++) {
            const int n = n0 + wn + ni * 8 + fcol;
            const float b0 = __ldg(&bias[n]);
            const float b1 = __ldg(&bias[n + 1]);
            #pragma unroll
            for (int half = 0; half < 2; half++) {
                const int m = m0 + wm + mi * 16 + frow + half * 8;
                float vx = (acc[mi][ni][half * 2 + 0] + b0) * scale;
                float vy = (acc[mi][ni][half * 2 + 1] + b1) * scale;
                if (MODE == 0) {
                    float2 val{vx, vy};
                    *reinterpret_cast<float2*>(&Cf[(size_t)m * H_ + n]) = val;
                } else {
                    const int b = m >> 11, s = m & 2047;
                    const int h = n >> 6, hd = n & 63;
                    size_t idx = (((size_t)(b * NH_ + h)) * S_ + s) * HD_ + hd;
                    uint32_t hi = prmt7632(__float_as_uint(vx), __float_as_uint(vy));
                    uint32_t lo = bf16x2_rn(vy - trunc_bf(vy), vx - trunc_bf(vx));
                    reinterpret_cast<uint32_t*>(g.ohi[z])[idx >> 1] = hi;
                    reinterpret_cast<uint32_t*>(g.olo[z])[idx >> 1] = lo;
                }
            }
        }
    }
}

// ---------------------------------------------------------------------------
// Tensor-core flash attention (causal), bf16x3, base-2 softmax (R4 verbatim).
// ---------------------------------------------------------------------------
constexpr int RP = 72, TSZ = 64 * RP * 2, KVOFF = 2 * TSZ;
constexpr int ATTN_SMEM = 2 * TSZ + 2 * 4 * TSZ;   // 92160

__global__ __launch_bounds__(128)
void attn_mma(const __nv_bfloat16* __restrict__ qhi, const __nv_bfloat16* __restrict__ qlo,
              const __nv_bfloat16* __restrict__ khi, const __nv_bfloat16* __restrict__ klo,
              const __nv_bfloat16* __restrict__ vhi, const __nv_bfloat16* __restrict__ vlo,
              __nv_bfloat16* __restrict__ ahi, __nv_bfloat16* __restrict__ alo)
{
    extern __shared__ char smem[];
    const uint32_t sb = smem_u32(smem);
    const int tid = threadIdx.x, wid = tid >> 5, lane = tid & 31;
    const int qt = 31 - blockIdx.x;
    const int bh = blockIdx.y;
    const int q0 = qt * 64;
    const size_t boff = (size_t)bh * S_ * HD_;
    const int wm = wid * 16;

    auto cp_tile = [&](uint32_t dst, const __nv_bfloat16* src) {
        #pragma unroll
        for (int t = 0; t < 4; t++) {
            int u = tid + t * 128, r = u >> 3, ch = u & 7;
            cp_async16(dst + (r * RP + ch * 8) * 2, src + (size_t)r * HD_ + ch * 8);
        }
    };
    cp_tile(sb,       qhi + boff + (size_t)q0 * HD_);
    cp_tile(sb + TSZ, qlo + boff + (size_t)q0 * HD_);
    CP_COMMIT();
    auto issue = [&](int kt) {
        uint32_t kb = sb + KVOFF + (kt & 1) * 4 * TSZ;
        const size_t o = boff + (size_t)kt * 64 * HD_;
        cp_tile(kb, khi + o);           cp_tile(kb + TSZ, klo + o);
        cp_tile(kb + 2 * TSZ, vhi + o); cp_tile(kb + 3 * TSZ, vlo + o);
        CP_COMMIT();
    };
    issue(0);
    CP_WAIT(1);
    __syncthreads();

    uint32_t qh[4][4], ql[4][4];
    #pragma unroll
    for (int ks = 0; ks < 4; ks++) {
        uint32_t a = sb + ((wm + (lane & 15)) * RP + ks * 16 + (lane >> 4) * 8) * 2;
        ldmatrix_x4(qh[ks], a);
        ldmatrix_x4(ql[ks], a + TSZ);
    }

    float o[8][4];
    #pragma unroll
    for (int j = 0; j < 8; j++)
        #pragma unroll
        for (int r = 0; r < 4; r++) o[j][r] = 0.f;
    float m_i[2] = {-1e30f, -1e30f}, l_i[2] = {0.f, 0.f};

    for (int kt = 0; kt <= qt; kt++) {
        if (kt < qt) { issue(kt + 1); CP_WAIT(1); }
        else         { CP_WAIT(0); }
        __syncthreads();
        const uint32_t kb = sb + KVOFF + (kt & 1) * 4 * TSZ;

        float s[8][4];
        #pragma unroll
        for (int j = 0; j < 8; j++)
            #pragma unroll
            for (int r = 0; r < 4; r++) s[j][r] = 0.f;

        #pragma unroll
        for (int ks = 0; ks < 4; ks++) {
            #pragma unroll
            for (int j = 0; j < 8; j++) {
                uint32_t bh2[2], bl2[2];
                int l = lane & 15;
                uint32_t ka = kb + ((8 * j + (l & 7)) * RP + ks * 16 + (l >> 3) * 8) * 2;
                ldmatrix_x2(bh2, ka);
                ldmatrix_x2(bl2, ka + TSZ);
                mma_bf16(s[j], qh[ks], bh2);
                mma_bf16(s[j], ql[ks], bh2);
                mma_bf16(s[j], qh[ks], bl2);
            }
        }

        if (kt == qt) {
            const int r0 = wm + (lane >> 2);
            #pragma unroll
            for (int j = 0; j < 8; j++) {
                const int kc = 8 * j + 2 * (lane & 3);
                if (kc     > r0)     s[j][0] = -1e30f;
                if (kc + 1 > r0)     s[j][1] = -1e30f;
                if (kc     > r0 + 8) s[j][2] = -1e30f;
                if (kc + 1 > r0 + 8) s[j][3] = -1e30f;
            }
        }

        float mx0 = -1e30f, mx1 = -1e30f;
        #pragma unroll
        for (int j = 0; j < 8; j++) {
            mx0 = fmaxf(mx0, fmaxf(s[j][0], s[j][1]));
            mx1 = fmaxf(mx1, fmaxf(s[j][2], s[j][3]));
        }
        mx0 = fmaxf(mx0, __shfl_xor_sync(~0u, mx0, 1));
        mx0 = fmaxf(mx0, __shfl_xor_sync(~0u, mx0, 2));
        mx1 = fmaxf(mx1, __shfl_xor_sync(~0u, mx1, 1));
        mx1 = fmaxf(mx1, __shfl_xor_sync(~0u, mx1, 2));
        const float nm0 = fmaxf(m_i[0], mx0), nm1 = fmaxf(m_i[1], mx1);
        const float c0 = ex2f(m_i[0] - nm0), c1 = ex2f(m_i[1] - nm1);
        m_i[0] = nm0; m_i[1] = nm1;

        float rs0 = 0.f, rs1 = 0.f;
        #pragma unroll
        for (int j = 0; j < 8; j++) {
            s[j][0] = ex2f(s[j][0] - nm0);
            s[j][1] = ex2f(s[j][1] - nm0);
            s[j][2] = ex2f(s[j][2] - nm1);
            s[j][3] = ex2f(s[j][3] - nm1);
            rs0 += s[j][0] + s[j][1];
            rs1 += s[j][2] + s[j][3];
        }
        rs0 += __shfl_xor_sync(~0u, rs0, 1);
        rs0 += __shfl_xor_sync(~0u, rs0, 2);
        rs1 += __shfl_xor_sync(~0u, rs1, 1);
        rs1 += __shfl_xor_sync(~0u, rs1, 2);
        l_i[0] = l_i[0] * c0 + rs0;
        l_i[1] = l_i[1] * c1 + rs1;
        #pragma unroll
        for (int j = 0; j < 8; j++) {
            o[j][0] *= c0; o[j][1] *= c0;
            o[j][2] *= c1; o[j][3] *= c1;
        }

        uint32_t ph[4][4], pl[4][4];
        #pragma unroll
        for (int k2 = 0; k2 < 4; k2++) {
            #pragma unroll
            for (int half = 0; half < 2; half++) {
                const int j = 2 * k2 + half;
                ph[k2][half*2+0] = prmt7632(__float_as_uint(s[j][0]), __float_as_uint(s[j][1]));
                ph[k2][half*2+1] = prmt7632(__float_as_uint(s[j][2]), __float_as_uint(s[j][3]));
                pl[k2][half*2+0] = bf16x2_rn(s[j][1] - trunc_bf(s[j][1]),
                                             s[j][0] - trunc_bf(s[j][0]));
                pl[k2][half*2+1] = bf16x2_rn(s[j][3] - trunc_bf(s[j][3]),
                                             s[j][2] - trunc_bf(s[j][2]));
            }
        }

        const uint32_t vb = kb + 2 * TSZ;
        #pragma unroll
        for (int k2 = 0; k2 < 4; k2++) {
            #pragma unroll
            for (int j = 0; j < 8; j++) {
                uint32_t vh2[2], vl2[2];
                uint32_t va = vb + ((k2 * 16 + (lane & 15)) * RP + 8 * j) * 2;
                ldmatrix_x2_trans(vh2, va);
                ldmatrix_x2_trans(vl2, va + TSZ);
                mma_bf16(o[j], ph[k2], vh2);
                mma_bf16(o[j], pl[k2], vh2);
                mma_bf16(o[j], ph[k2], vl2);
            }
        }
        __syncthreads();
    }

    const float inv0 = 1.f / l_i[0], inv1 = 1.f / l_i[1];
    const int b = bh >> 4, h = bh & 15;
    const int r0 = q0 + wm + (lane >> 2);
    const size_t base0 = ((size_t)(b * S_) + r0) * H_ + h * 64;
    const size_t base1 = base0 + (size_t)8 * H_;
    #pragma unroll
    for (int j = 0; j < 8; j++) {
        const int c = 8 * j + 2 * (lane & 3);
        float f00 = o[j][0] * inv0, f01 = o[j][1] * inv0;
        float f10 = o[j][2] * inv1, f11 = o[j][3] * inv1;
        reinterpret_cast<uint32_t*>(ahi)[(base0 + c) >> 1] =
            prmt7632(__float_as_uint(f00), __float_as_uint(f01));
        reinterpret_cast<uint32_t*>(alo)[(base0 + c) >> 1] =
            bf16x2_rn(f01 - trunc_bf(f01), f00 - trunc_bf(f00));
        reinterpret_cast<uint32_t*>(ahi)[(base1 + c) >> 1] =
            prmt7632(__float_as_uint(f10), __float_as_uint(f11));
        reinterpret_cast<uint32_t*>(alo)[(base1 + c) >> 1] =
            bf16x2_rn(f11 - trunc_bf(f11), f10 - trunc_bf(f10));
    }
}

// ---------------------------------------------------------------------------
extern "C" void kernel_launch(void* const* d_in, const int* in_sizes, int n_in,
                              void* d_out, int out_size)
{
    const float* x  = (const float*)d_in[0];
    const float* Wq = (const float*)d_in[1];
    const float* bq = (const float*)d_in[2];
    const float* Wk = (const float*)d_in[3];
    const float* bk = (const float*)d_in[4];
    const float* Wv = (const float*)d_in[5];
    const float* bv = (const float*)d_in[6];
    const float* Wo = (const float*)d_in[7];
    const float* bo = (const float*)d_in[8];
    float* out = (float*)d_out;

    __nv_bfloat16 *xhi, *xlo, *whi, *wlo;
    __nv_bfloat16 *q_hi, *q_lo, *k_hi, *k_lo, *v_hi, *v_lo, *a_hi, *a_lo;
    cudaGetSymbolAddress((void**)&xhi, g_xhi);
    cudaGetSymbolAddress((void**)&xlo, g_xlo);
    cudaGetSymbolAddress((void**)&whi, g_whi);
    cudaGetSymbolAddress((void**)&wlo, g_wlo);
    cudaGetSymbolAddress((void**)&q_hi, g_qhi);
    cudaGetSymbolAddress((void**)&q_lo, g_qlo);
    cudaGetSymbolAddress((void**)&k_hi, g_khi);
    cudaGetSymbolAddress((void**)&k_lo, g_klo);
    cudaGetSymbolAddress((void**)&v_hi, g_vhi);
    cudaGetSymbolAddress((void**)&v_lo, g_vlo);
    cudaGetSymbolAddress((void**)&a_hi, g_ahi);
    cudaGetSymbolAddress((void**)&a_lo, g_alo);

    cudaFuncSetAttribute(gemm3<0>, cudaFuncAttributeMaxDynamicSharedMemorySize, GEMM_SMEM);
    cudaFuncSetAttribute(gemm3<1>, cudaFuncAttributeMaxDynamicSharedMemorySize, GEMM_SMEM);
    cudaFuncSetAttribute(attn_mma, cudaFuncAttributeMaxDynamicSharedMemorySize, ATTN_SMEM);

    const size_t WN = (size_t)H_ * H_;

    {
        int n4 = (M_ * H_) / 4;
        split_x<<<(n4 + 255) / 256, 256>>>(x, xhi, xlo, n4);
        WSplit ws;
        ws.src[0] = Wq; ws.src[1] = Wk; ws.src[2] = Wv; ws.src[3] = Wo;
        int w4 = (H_ * H_) / 4;
        dim3 wg((w4 + 255) / 256, 4);
        split_w<<<wg, 256>>>(ws, whi, wlo, w4);
    }

    // Fused QKV projection (grid.z selects weight)
    G3 g;
    g.bias[0] = bq;  g.bias[1] = bk;  g.bias[2] = bv;
    g.ohi[0] = q_hi; g.ohi[1] = k_hi; g.ohi[2] = v_hi;
    g.olo[0] = q_lo; g.olo[1] = k_lo; g.olo[2] = v_lo;
    g.scale[0] = SCALE_Q; g.scale[1] = 1.0f; g.scale[2] = 1.0f;
    dim3 gq(H_ / 128, M_ / 128, 3);
    gemm3<1><<<gq, 256, GEMM_SMEM>>>(xhi, xlo, whi, wlo, g, nullptr);

    dim3 ag(S_ / 64, B_ * NH_);
    attn_mma<<<ag, 128, ATTN_SMEM>>>(q_hi, q_lo, k_hi, k_lo, v_hi, v_lo,
                                     a_hi, a_lo);

    // Output projection
    G3 go;
    go.bias[0] = bo; go.bias[1] = bo; go.bias[2] = bo;
    go.ohi[0] = nullptr; go.ohi[1] = nullptr; go.ohi[2] = nullptr;
    go.olo[0] = nullptr; go.olo[1] = nullptr; go.olo[2] = nullptr;
    go.scale[0] = 1.0f; go.scale[1] = 1.0f; go.scale[2] = 1.0f;
    dim3 gg(H_ / 128, M_ / 128, 1);
    gemm3<0><<<gg, 256, GEMM_SMEM>>>(a_hi, a_lo, whi + 3 * WN, wlo + 3 * WN, go, out);
}

// round 8
// speedup vs baseline: 2.0495x; 1.0965x over previous
#include <cuda_runtime.h>
#include <cuda_bf16.h>
#include <cstdint>
#include <cstddef>

constexpr int B_ = 4, S_ = 2048, H_ = 1024, NH_ = 16, HD_ = 64;
constexpr int M_ = B_ * S_;
constexpr float SCALE_Q = 0.18033688011112042f;  // 0.125 * log2(e)

// Scratch (device globals)
__device__ __nv_bfloat16 g_xhi[(size_t)M_ * H_];
__device__ __nv_bfloat16 g_xlo[(size_t)M_ * H_];
__device__ __nv_bfloat16 g_whi[4 * (size_t)H_ * H_];
__device__ __nv_bfloat16 g_wlo[4 * (size_t)H_ * H_];
__device__ __nv_bfloat16 g_qhi[(size_t)M_ * H_];
__device__ __nv_bfloat16 g_qlo[(size_t)M_ * H_];
__device__ __nv_bfloat16 g_khi[(size_t)M_ * H_];
__device__ __nv_bfloat16 g_klo[(size_t)M_ * H_];
__device__ __nv_bfloat16 g_vhi[(size_t)M_ * H_];
__device__ __nv_bfloat16 g_vlo[(size_t)M_ * H_];
__device__ __nv_bfloat16 g_ahi[(size_t)M_ * H_];
__device__ __nv_bfloat16 g_alo[(size_t)M_ * H_];

__device__ __forceinline__ uint32_t smem_u32(const void* p) {
    uint32_t a;
    asm("{ .reg .u64 t; cvta.to.shared.u64 t, %1; cvt.u32.u64 %0, t; }"
        : "=r"(a) : "l"(p));
    return a;
}
__device__ __forceinline__ void cp_async16(uint32_t dst, const void* src) {
    asm volatile("cp.async.cg.shared.global [%0], [%1], 16;"
                 :: "r"(dst), "l"(src) : "memory");
}
#define CP_COMMIT() asm volatile("cp.async.commit_group;" ::: "memory")
#define CP_WAIT(n)  asm volatile("cp.async.wait_group %0;" :: "n"(n) : "memory")

__device__ __forceinline__ void ldmatrix_x4(uint32_t* r, uint32_t a) {
    asm volatile("ldmatrix.sync.aligned.m8n8.x4.shared.b16 {%0,%1,%2,%3}, [%4];"
                 : "=r"(r[0]), "=r"(r[1]), "=r"(r[2]), "=r"(r[3]) : "r"(a));
}
__device__ __forceinline__ void ldmatrix_x2(uint32_t* r, uint32_t a) {
    asm volatile("ldmatrix.sync.aligned.m8n8.x2.shared.b16 {%0,%1}, [%2];"
                 : "=r"(r[0]), "=r"(r[1]) : "r"(a));
}
__device__ __forceinline__ void ldmatrix_x2_trans(uint32_t* r, uint32_t a) {
    asm volatile("ldmatrix.sync.aligned.m8n8.x2.trans.shared.b16 {%0,%1}, [%2];"
                 : "=r"(r[0]), "=r"(r[1]) : "r"(a));
}
__device__ __forceinline__ void mma_bf16(float* c, const uint32_t* a,
                                         const uint32_t* b) {
    asm volatile(
        "mma.sync.aligned.m16n8k16.row.col.f32.bf16.bf16.f32 "
        "{%0,%1,%2,%3}, {%4,%5,%6,%7}, {%8,%9}, {%0,%1,%2,%3};"
        : "+f"(c[0]), "+f"(c[1]), "+f"(c[2]), "+f"(c[3])
        : "r"(a[0]), "r"(a[1]), "r"(a[2]), "r"(a[3]), "r"(b[0]), "r"(b[1]));
}
__device__ __forceinline__ float ex2f(float x) {
    float y; asm("ex2.approx.ftz.f32 %0, %1;" : "=f"(y) : "f"(x)); return y;
}
__device__ __forceinline__ float trunc_bf(float x) {
    return __uint_as_float(__float_as_uint(x) & 0xFFFF0000u);
}
__device__ __forceinline__ uint32_t prmt7632(uint32_t a, uint32_t b) {
    uint32_t d;
    asm("prmt.b32 %0, %1, %2, 0x7632;" : "=r"(d) : "r"(a), "r"(b));
    return d;
}
__device__ __forceinline__ uint32_t bf16x2_rn(float h, float l) {
    uint32_t d;
    asm("cvt.rn.satfinite.bf16x2.f32 %0, %1, %2;" : "=r"(d) : "f"(h), "f"(l));
    return d;
}

// ---------------------------------------------------------------------------
// Splits
// ---------------------------------------------------------------------------
__global__ __launch_bounds__(256)
void split_x(const float* __restrict__ src, __nv_bfloat16* __restrict__ hi,
             __nv_bfloat16* __restrict__ lo, int n4)
{
    int i = blockIdx.x * blockDim.x + threadIdx.x;
    if (i >= n4) return;
    float4 v = reinterpret_cast<const float4*>(src)[i];
    float t0 = trunc_bf(v.x), t1 = trunc_bf(v.y), t2 = trunc_bf(v.z), t3 = trunc_bf(v.w);
    uint2 hu, lu;
    hu.x = prmt7632(__float_as_uint(v.x), __float_as_uint(v.y));
    hu.y = prmt7632(__float_as_uint(v.z), __float_as_uint(v.w));
    lu.x = bf16x2_rn(v.y - t1, v.x - t0);
    lu.y = bf16x2_rn(v.w - t3, v.z - t2);
    reinterpret_cast<uint2*>(hi)[i] = hu;
    reinterpret_cast<uint2*>(lo)[i] = lu;
}

struct WSplit { const float* src[4]; };

__global__ __launch_bounds__(256)
void split_w(WSplit ws, __nv_bfloat16* __restrict__ hiBase,
             __nv_bfloat16* __restrict__ loBase, int n4)
{
    const int w = blockIdx.y;
    const float* src = ws.src[w];
    __nv_bfloat16* hi = hiBase + (size_t)w * H_ * H_;
    __nv_bfloat16* lo = loBase + (size_t)w * H_ * H_;
    int i = blockIdx.x * blockDim.x + threadIdx.x;
    if (i >= n4) return;
    float4 v = reinterpret_cast<const float4*>(src)[i];
    float t0 = trunc_bf(v.x), t1 = trunc_bf(v.y), t2 = trunc_bf(v.z), t3 = trunc_bf(v.w);
    uint2 hu, lu;
    hu.x = prmt7632(__float_as_uint(v.x), __float_as_uint(v.y));
    hu.y = prmt7632(__float_as_uint(v.z), __float_as_uint(v.w));
    lu.x = bf16x2_rn(v.y - t1, v.x - t0);
    lu.y = bf16x2_rn(v.w - t3, v.z - t2);
    reinterpret_cast<uint2*>(hi)[i] = hu;
    reinterpret_cast<uint2*>(lo)[i] = lu;
}

// ---------------------------------------------------------------------------
// bf16x3 GEMM, pass-interleaved per K-chunk (unchanged from R7 — at ceiling).
// ---------------------------------------------------------------------------
constexpr int RPB = 40;
constexpr int TB  = 128 * RPB * 2;
constexpr int O_AH = 0, O_AL = TB, O_WH = 2 * TB, O_WL = 3 * TB;
constexpr int GBUF = 4 * TB;
constexpr int GEMM_SMEM = 2 * GBUF;

struct G3 {
    const float* bias[3];
    __nv_bfloat16* ohi[3];
    __nv_bfloat16* olo[3];
    float scale[3];
};

template <int MODE>
__global__ __launch_bounds__(256)
void gemm3(const __nv_bfloat16* __restrict__ Ahi,
           const __nv_bfloat16* __restrict__ Alo,
           const __nv_bfloat16* __restrict__ WhiB,
           const __nv_bfloat16* __restrict__ WloB,
           G3 g, float* __restrict__ Cf)
{
    extern __shared__ char smem[];
    const uint32_t sb = smem_u32(smem);
    const int tid = threadIdx.x, wid = tid >> 5, lane = tid & 31;
    const int z = (MODE == 1) ? blockIdx.z : 0;
    const int m0 = blockIdx.y * 128, n0 = blockIdx.x * 128;
    const int wm = (wid & 1) * 64, wn = (wid >> 1) * 32;
    const size_t WN = (size_t)H_ * H_;
    const __nv_bfloat16* Whi = WhiB + (size_t)z * WN;
    const __nv_bfloat16* Wlo = WloB + (size_t)z * WN;

    float acc[4][4][4];
    #pragma unroll
    for (int mi = 0; mi < 4; mi++)
        #pragma unroll
        for (int ni = 0; ni < 4; ni++)
            #pragma unroll
            for (int r = 0; r < 4; r++) acc[mi][ni][r] = 0.f;

    auto issue = [&](int c) {
        const int k0 = c * 32;
        const uint32_t bs = sb + (c & 1) * GBUF;
        #pragma unroll
        for (int t = 0; t < 2; t++) {
            int u = tid + t * 256;
            int row = u >> 2, seg = u & 3;
            uint32_t d = (row * RPB + seg * 8) * 2;
            size_t ga = (size_t)(m0 + row) * H_ + k0 + seg * 8;
            size_t gw = (size_t)(n0 + row) * H_ + k0 + seg * 8;
            cp_async16(bs + O_AH + d, Ahi + ga);
            cp_async16(bs + O_AL + d, Alo + ga);
            cp_async16(bs + O_WH + d, Whi + gw);
            cp_async16(bs + O_WL + d, Wlo + gw);
        }
        CP_COMMIT();
    };

    issue(0);
    constexpr int NCH = H_ / 32;

    for (int c = 0; c < NCH; c++) {
        if (c + 1 < NCH) { issue(c + 1); CP_WAIT(1); }
        else             { CP_WAIT(0); }
        __syncthreads();
        const uint32_t bs = sb + (c & 1) * GBUF;

        #pragma unroll
        for (int ks = 0; ks < 2; ks++) {
            const int l = lane & 15;
            uint32_t ah[4][4], bh[4][2];
            #pragma unroll
            for (int mi = 0; mi < 4; mi++)
                ldmatrix_x4(ah[mi], bs + O_AH +
                    ((wm + mi * 16 + l) * RPB + ks * 16 + (lane >> 4) * 8) * 2);
            #pragma unroll
            for (int ni = 0; ni < 4; ni++)
                ldmatrix_x2(bh[ni], bs + O_WH +
                    ((wn + ni * 8 + (l & 7)) * RPB + ks * 16 + (l >> 3) * 8) * 2);
            #pragma unroll
            for (int mi = 0; mi < 4; mi++)
                #pragma unroll
                for (int ni = 0; ni < 4; ni++)
                    mma_bf16(acc[mi][ni], ah[mi], bh[ni]);

            uint32_t bl[4][2];
            #pragma unroll
            for (int ni = 0; ni < 4; ni++)
                ldmatrix_x2(bl[ni], bs + O_WL +
                    ((wn + ni * 8 + (l & 7)) * RPB + ks * 16 + (l >> 3) * 8) * 2);
            #pragma unroll
            for (int mi = 0; mi < 4; mi++)
                #pragma unroll
                for (int ni = 0; ni < 4; ni++)
                    mma_bf16(acc[mi][ni], ah[mi], bl[ni]);

            uint32_t al[4][4];
            #pragma unroll
            for (int mi = 0; mi < 4; mi++)
                ldmatrix_x4(al[mi], bs + O_AL +
                    ((wm + mi * 16 + l) * RPB + ks * 16 + (lane >> 4) * 8) * 2);
            #pragma unroll
            for (int mi = 0; mi < 4; mi++)
                #pragma unroll
                for (int ni = 0; ni < 4; ni++)
                    mma_bf16(acc[mi][ni], al[mi], bh[ni]);
        }
        __syncthreads();
    }

    const float scale = g.scale[z];
    const float* bias = g.bias[z];
    const int frow = lane >> 2, fcol = (lane & 3) * 2;
    #pragma unroll
    for (int mi = 0; mi < 4; mi++) {
        #pragma unroll
        for (int ni = 0; ni < 4; ni++) {
            const int n = n0 + wn + ni * 8 + fcol;
            const float b0 = __ldg(&bias[n]);
            const float b1 = __ldg(&bias[n + 1]);
            #pragma unroll
            for (int half = 0; half < 2; half++) {
                const int m = m0 + wm + mi * 16 + frow + half * 8;
                float vx = (acc[mi][ni][half * 2 + 0] + b0) * scale;
                float vy = (acc[mi][ni][half * 2 + 1] + b1) * scale;
                if (MODE == 0) {
                    float2 val{vx, vy};
                    *reinterpret_cast<float2*>(&Cf[(size_t)m * H_ + n]) = val;
                } else {
                    const int b = m >> 11, s = m & 2047;
                    const int h = n >> 6, hd = n & 63;
                    size_t idx = (((size_t)(b * NH_ + h)) * S_ + s) * HD_ + hd;
                    uint32_t hi = prmt7632(__float_as_uint(vx), __float_as_uint(vy));
                    uint32_t lo = bf16x2_rn(vy - trunc_bf(vy), vx - trunc_bf(vx));
                    reinterpret_cast<uint32_t*>(g.ohi[z])[idx >> 1] = hi;
                    reinterpret_cast<uint32_t*>(g.olo[z])[idx >> 1] = lo;
                }
            }
        }
    }
}

// ---------------------------------------------------------------------------
// Flash attention (bf16x3, base-2 softmax). Q smem OVERLAID on KV buffer 1:
// smem/CTA 92160 -> 73728 B => 3 CTAs/SM (3 warps/SMSP, was 2).
// ---------------------------------------------------------------------------
constexpr int RP = 72, TSZ = 64 * RP * 2;       // 9216 B per 64x64 tile
constexpr int KVBUF = 4 * TSZ;                  // 36864 per buffer
constexpr int ATTN_SMEM = 2 * KVBUF;            // 73728

__global__ __launch_bounds__(128, 3)
void attn_mma(const __nv_bfloat16* __restrict__ qhi, const __nv_bfloat16* __restrict__ qlo,
              const __nv_bfloat16* __restrict__ khi, const __nv_bfloat16* __restrict__ klo,
              const __nv_bfloat16* __restrict__ vhi, const __nv_bfloat16* __restrict__ vlo,
              __nv_bfloat16* __restrict__ ahi, __nv_bfloat16* __restrict__ alo)
{
    extern __shared__ char smem[];
    const uint32_t sb = smem_u32(smem);
    const int tid = threadIdx.x, wid = tid >> 5, lane = tid & 31;
    const int qt = 31 - blockIdx.x;
    const int bh = blockIdx.y;
    const int q0 = qt * 64;
    const size_t boff = (size_t)bh * S_ * HD_;
    const int wm = wid * 16;

    auto cp_tile = [&](uint32_t dst, const __nv_bfloat16* src) {
        #pragma unroll
        for (int t = 0; t < 4; t++) {
            int u = tid + t * 128, r = u >> 3, ch = u & 7;
            cp_async16(dst + (r * RP + ch * 8) * 2, src + (size_t)r * HD_ + ch * 8);
        }
    };
    // Q lives inside KV buffer 1's region (first written at issue(1), by which
    // time Q fragments are register-resident).
    const uint32_t qoff = sb + KVBUF;
    cp_tile(qoff,       qhi + boff + (size_t)q0 * HD_);
    cp_tile(qoff + TSZ, qlo + boff + (size_t)q0 * HD_);
    CP_COMMIT();
    auto issue = [&](int kt) {
        uint32_t kb = sb + (kt & 1) * KVBUF;
        const size_t o = boff + (size_t)kt * 64 * HD_;
        cp_tile(kb, khi + o);           cp_tile(kb + TSZ, klo + o);
        cp_tile(kb + 2 * TSZ, vhi + o); cp_tile(kb + 3 * TSZ, vlo + o);
        CP_COMMIT();
    };
    issue(0);
    CP_WAIT(1);        // Q complete (KV0 may still be in flight)
    __syncthreads();

    uint32_t qh[4][4], ql[4][4];
    #pragma unroll
    for (int ks = 0; ks < 4; ks++) {
        uint32_t a = qoff + ((wm + (lane & 15)) * RP + ks * 16 + (lane >> 4) * 8) * 2;
        ldmatrix_x4(qh[ks], a);
        ldmatrix_x4(ql[ks], a + TSZ);
    }
    __syncthreads();   // all warps done reading Q before issue(1) overwrites it

    float o[8][4];
    #pragma unroll
    for (int j = 0; j < 8; j++)
        #pragma unroll
        for (int r = 0; r < 4; r++) o[j][r] = 0.f;
    float m_i[2] = {-1e30f, -1e30f}, l_i[2] = {0.f, 0.f};

    for (int kt = 0; kt <= qt; kt++) {
        if (kt < qt) { issue(kt + 1); CP_WAIT(1); }
        else         { CP_WAIT(0); }
        __syncthreads();
        const uint32_t kb = sb + (kt & 1) * KVBUF;

        float s[8][4];
        #pragma unroll
        for (int j = 0; j < 8; j++)
            #pragma unroll
            for (int r = 0; r < 4; r++) s[j][r] = 0.f;

        #pragma unroll
        for (int ks = 0; ks < 4; ks++) {
            #pragma unroll
            for (int j = 0; j < 8; j++) {
                uint32_t bh2[2], bl2[2];
                int l = lane & 15;
                uint32_t ka = kb + ((8 * j + (l & 7)) * RP + ks * 16 + (l >> 3) * 8) * 2;
                ldmatrix_x2(bh2, ka);
                ldmatrix_x2(bl2, ka + TSZ);
                mma_bf16(s[j], qh[ks], bh2);
                mma_bf16(s[j], ql[ks], bh2);
                mma_bf16(s[j], qh[ks], bl2);
            }
        }

        if (kt == qt) {
            const int r0 = wm + (lane >> 2);
            #pragma unroll
            for (int j = 0; j < 8; j++) {
                const int kc = 8 * j + 2 * (lane & 3);
                if (kc     > r0)     s[j][0] = -1e30f;
                if (kc + 1 > r0)     s[j][1] = -1e30f;
                if (kc     > r0 + 8) s[j][2] = -1e30f;
                if (kc + 1 > r0 + 8) s[j][3] = -1e30f;
            }
        }

        float mx0 = -1e30f, mx1 = -1e30f;
        #pragma unroll
        for (int j = 0; j < 8; j++) {
            mx0 = fmaxf(mx0, fmaxf(s[j][0], s[j][1]));
            mx1 = fmaxf(mx1, fmaxf(s[j][2], s[j][3]));
        }
        mx0 = fmaxf(mx0, __shfl_xor_sync(~0u, mx0, 1));
        mx0 = fmaxf(mx0, __shfl_xor_sync(~0u, mx0, 2));
        mx1 = fmaxf(mx1, __shfl_xor_sync(~0u, mx1, 1));
        mx1 = fmaxf(mx1, __shfl_xor_sync(~0u, mx1, 2));
        const float nm0 = fmaxf(m_i[0], mx0), nm1 = fmaxf(m_i[1], mx1);
        const float c0 = ex2f(m_i[0] - nm0), c1 = ex2f(m_i[1] - nm1);
        m_i[0] = nm0; m_i[1] = nm1;

        float rs0 = 0.f, rs1 = 0.f;
        #pragma unroll
        for (int j = 0; j < 8; j++) {
            s[j][0] = ex2f(s[j][0] - nm0);
            s[j][1] = ex2f(s[j][1] - nm0);
            s[j][2] = ex2f(s[j][2] - nm1);
            s[j][3] = ex2f(s[j][3] - nm1);
            rs0 += s[j][0] + s[j][1];
            rs1 += s[j][2] + s[j][3];
        }
        rs0 += __shfl_xor_sync(~0u, rs0, 1);
        rs0 += __shfl_xor_sync(~0u, rs0, 2);
        rs1 += __shfl_xor_sync(~0u, rs1, 1);
        rs1 += __shfl_xor_sync(~0u, rs1, 2);
        l_i[0] = l_i[0] * c0 + rs0;
        l_i[1] = l_i[1] * c1 + rs1;
        #pragma unroll
        for (int j = 0; j < 8; j++) {
            o[j][0] *= c0; o[j][1] *= c0;
            o[j][2] *= c1; o[j][3] *= c1;
        }

        uint32_t ph[4][4], pl[4][4];
        #pragma unroll
        for (int k2 = 0; k2 < 4; k2++) {
            #pragma unroll
            for (int half = 0; half < 2; half++) {
                const int j = 2 * k2 + half;
                ph[k2][half*2+0] = prmt7632(__float_as_uint(s[j][0]), __float_as_uint(s[j][1]));
                ph[k2][half*2+1] = prmt7632(__float_as_uint(s[j][2]), __float_as_uint(s[j][3]));
                pl[k2][half*2+0] = bf16x2_rn(s[j][1] - trunc_bf(s[j][1]),
                                             s[j][0] - trunc_bf(s[j][0]));
                pl[k2][half*2+1] = bf16x2_rn(s[j][3] - trunc_bf(s[j][3]),
                                             s[j][2] - trunc_bf(s[j][2]));
            }
        }

        const uint32_t vb = kb + 2 * TSZ;
        #pragma unroll
        for (int k2 = 0; k2 < 4; k2++) {
            #pragma unroll
            for (int j = 0; j < 8; j++) {
                uint32_t vh2[2], vl2[2];
                uint32_t va = vb + ((k2 * 16 + (lane & 15)) * RP + 8 * j) * 2;
                ldmatrix_x2_trans(vh2, va);
                ldmatrix_x2_trans(vl2, va + TSZ);
                mma_bf16(o[j], ph[k2], vh2);
                mma_bf16(o[j], pl[k2], vh2);
                mma_bf16(o[j], ph[k2], vl2);
            }
        }
        __syncthreads();
    }

    const float inv0 = 1.f / l_i[0], inv1 = 1.f / l_i[1];
    const int b = bh >> 4, h = bh & 15;
    const int r0 = q0 + wm + (lane >> 2);
    const size_t base0 = ((size_t)(b * S_) + r0) * H_ + h * 64;
    const size_t base1 = base0 + (size_t)8 * H_;
    #pragma unroll
    for (int j = 0; j < 8; j++) {
        const int c = 8 * j + 2 * (lane & 3);
        float f00 = o[j][0] * inv0, f01 = o[j][1] * inv0;
        float f10 = o[j][2] * inv1, f11 = o[j][3] * inv1;
        reinterpret_cast<uint32_t*>(ahi)[(base0 + c) >> 1] =
            prmt7632(__float_as_uint(f00), __float_as_uint(f01));
        reinterpret_cast<uint32_t*>(alo)[(base0 + c) >> 1] =
            bf16x2_rn(f01 - trunc_bf(f01), f00 - trunc_bf(f00));
        reinterpret_cast<uint32_t*>(ahi)[(base1 + c) >> 1] =
            prmt7632(__float_as_uint(f10), __float_as_uint(f11));
        reinterpret_cast<uint32_t*>(alo)[(base1 + c) >> 1] =
            bf16x2_rn(f11 - trunc_bf(f11), f10 - trunc_bf(f10));
    }
}

// ---------------------------------------------------------------------------
extern "C" void kernel_launch(void* const* d_in, const int* in_sizes, int n_in,
                              void* d_out, int out_size)
{
    const float* x  = (const float*)d_in[0];
    const float* Wq = (const float*)d_in[1];
    const float* bq = (const float*)d_in[2];
    const float* Wk = (const float*)d_in[3];
    const float* bk = (const float*)d_in[4];
    const float* Wv = (const float*)d_in[5];
    const float* bv = (const float*)d_in[6];
    const float* Wo = (const float*)d_in[7];
    const float* bo = (const float*)d_in[8];
    float* out = (float*)d_out;

    __nv_bfloat16 *xhi, *xlo, *whi, *wlo;
    __nv_bfloat16 *q_hi, *q_lo, *k_hi, *k_lo, *v_hi, *v_lo, *a_hi, *a_lo;
    cudaGetSymbolAddress((void**)&xhi, g_xhi);
    cudaGetSymbolAddress((void**)&xlo, g_xlo);
    cudaGetSymbolAddress((void**)&whi, g_whi);
    cudaGetSymbolAddress((void**)&wlo, g_wlo);
    cudaGetSymbolAddress((void**)&q_hi, g_qhi);
    cudaGetSymbolAddress((void**)&q_lo, g_qlo);
    cudaGetSymbolAddress((void**)&k_hi, g_khi);
    cudaGetSymbolAddress((void**)&k_lo, g_klo);
    cudaGetSymbolAddress((void**)&v_hi, g_vhi);
    cudaGetSymbolAddress((void**)&v_lo, g_vlo);
    cudaGetSymbolAddress((void**)&a_hi, g_ahi);
    cudaGetSymbolAddress((void**)&a_lo, g_alo);

    cudaFuncSetAttribute(gemm3<0>, cudaFuncAttributeMaxDynamicSharedMemorySize, GEMM_SMEM);
    cudaFuncSetAttribute(gemm3<1>, cudaFuncAttributeMaxDynamicSharedMemorySize, GEMM_SMEM);
    cudaFuncSetAttribute(attn_mma, cudaFuncAttributeMaxDynamicSharedMemorySize, ATTN_SMEM);

    const size_t WN = (size_t)H_ * H_;

    {
        int n4 = (M_ * H_) / 4;
        split_x<<<(n4 + 255) / 256, 256>>>(x, xhi, xlo, n4);
        WSplit ws;
        ws.src[0] = Wq; ws.src[1] = Wk; ws.src[2] = Wv; ws.src[3] = Wo;
        int w4 = (H_ * H_) / 4;
        dim3 wg((w4 + 255) / 256, 4);
        split_w<<<wg, 256>>>(ws, whi, wlo, w4);
    }

    G3 g;
    g.bias[0] = bq;  g.bias[1] = bk;  g.bias[2] = bv;
    g.ohi[0] = q_hi; g.ohi[1] = k_hi; g.ohi[2] = v_hi;
    g.olo[0] = q_lo; g.olo[1] = k_lo; g.olo[2] = v_lo;
    g.scale[0] = SCALE_Q; g.scale[1] = 1.0f; g.scale[2] = 1.0f;
    dim3 gq(H_ / 128, M_ / 128, 3);
    gemm3<1><<<gq, 256, GEMM_SMEM>>>(xhi, xlo, whi, wlo, g, nullptr);

    dim3 ag(S_ / 64, B_ * NH_);
    attn_mma<<<ag, 128, ATTN_SMEM>>>(q_hi, q_lo, k_hi, k_lo, v_hi, v_lo,
                                     a_hi, a_lo);

    G3 go;
    go.bias[0] = bo; go.bias[1] = bo; go.bias[2] = bo;
    go.ohi[0] = nullptr; go.ohi[1] = nullptr; go.ohi[2] = nullptr;
    go.olo[0] = nullptr; go.olo[1] = nullptr; go.olo[2] = nullptr;
    go.scale[0] = 1.0f; go.scale[1] = 1.0f; go.scale[2] = 1.0f;
    dim3 gg(H_ / 128, M_ / 128, 1);
    gemm3<0><<<gg, 256, GEMM_SMEM>>>(a_hi, a_lo, whi + 3 * WN, wlo + 3 * WN, go, out);
}

// round 9
// speedup vs baseline: 2.6000x; 1.2686x over previous
#include <cuda_runtime.h>
#include <cuda_bf16.h>
#include <cuda_fp16.h>
#include <cstdint>
#include <cstddef>

constexpr int B_ = 4, S_ = 2048, H_ = 1024, NH_ = 16, HD_ = 64;
constexpr int M_ = B_ * S_;
constexpr float SCALE_Q = 0.18033688011112042f;  // 0.125 * log2(e)
constexpr float WSC = 32.0f, INV_WSC = 1.0f / 32.0f;

// Scratch
__device__ __half        g_xh[(size_t)M_ * H_];      // fp16(x)
__device__ __half        g_wh[4 * (size_t)H_ * H_];  // fp16(32*W)
__device__ __half        g_wl[4 * (size_t)H_ * H_];  // fp16 residual
__device__ __nv_bfloat16 g_qhi[(size_t)M_ * H_];
__device__ __nv_bfloat16 g_qlo[(size_t)M_ * H_];
__device__ __nv_bfloat16 g_khi[(size_t)M_ * H_];
__device__ __nv_bfloat16 g_klo[(size_t)M_ * H_];
__device__ __nv_bfloat16 g_vhi[(size_t)M_ * H_];
__device__ __nv_bfloat16 g_vlo[(size_t)M_ * H_];
__device__ __half        g_ah[(size_t)M_ * H_];      // attention out fp16

__device__ __forceinline__ uint32_t smem_u32(const void* p) {
    uint32_t a;
    asm("{ .reg .u64 t; cvta.to.shared.u64 t, %1; cvt.u32.u64 %0, t; }"
        : "=r"(a) : "l"(p));
    return a;
}
__device__ __forceinline__ void cp_async16(uint32_t dst, const void* src) {
    asm volatile("cp.async.cg.shared.global [%0], [%1], 16;"
                 :: "r"(dst), "l"(src) : "memory");
}
#define CP_COMMIT() asm volatile("cp.async.commit_group;" ::: "memory")
#define CP_WAIT(n)  asm volatile("cp.async.wait_group %0;" :: "n"(n) : "memory")

__device__ __forceinline__ void ldmatrix_x4(uint32_t* r, uint32_t a) {
    asm volatile("ldmatrix.sync.aligned.m8n8.x4.shared.b16 {%0,%1,%2,%3}, [%4];"
                 : "=r"(r[0]), "=r"(r[1]), "=r"(r[2]), "=r"(r[3]) : "r"(a));
}
__device__ __forceinline__ void ldmatrix_x2(uint32_t* r, uint32_t a) {
    asm volatile("ldmatrix.sync.aligned.m8n8.x2.shared.b16 {%0,%1}, [%2];"
                 : "=r"(r[0]), "=r"(r[1]) : "r"(a));
}
__device__ __forceinline__ void ldmatrix_x2_trans(uint32_t* r, uint32_t a) {
    asm volatile("ldmatrix.sync.aligned.m8n8.x2.trans.shared.b16 {%0,%1}, [%2];"
                 : "=r"(r[0]), "=r"(r[1]) : "r"(a));
}
__device__ __forceinline__ void mma_bf16(float* c, const uint32_t* a,
                                         const uint32_t* b) {
    asm volatile(
        "mma.sync.aligned.m16n8k16.row.col.f32.bf16.bf16.f32 "
        "{%0,%1,%2,%3}, {%4,%5,%6,%7}, {%8,%9}, {%0,%1,%2,%3};"
        : "+f"(c[0]), "+f"(c[1]), "+f"(c[2]), "+f"(c[3])
        : "r"(a[0]), "r"(a[1]), "r"(a[2]), "r"(a[3]), "r"(b[0]), "r"(b[1]));
}
__device__ __forceinline__ void mma_f16(float* c, const uint32_t* a,
                                        const uint32_t* b) {
    asm volatile(
        "mma.sync.aligned.m16n8k16.row.col.f32.f16.f16.f32 "
        "{%0,%1,%2,%3}, {%4,%5,%6,%7}, {%8,%9}, {%0,%1,%2,%3};"
        : "+f"(c[0]), "+f"(c[1]), "+f"(c[2]), "+f"(c[3])
        : "r"(a[0]), "r"(a[1]), "r"(a[2]), "r"(a[3]), "r"(b[0]), "r"(b[1]));
}
__device__ __forceinline__ float ex2f(float x) {
    float y; asm("ex2.approx.ftz.f32 %0, %1;" : "=f"(y) : "f"(x)); return y;
}
__device__ __forceinline__ float trunc_bf(float x) {
    return __uint_as_float(__float_as_uint(x) & 0xFFFF0000u);
}
__device__ __forceinline__ uint32_t prmt7632(uint32_t a, uint32_t b) {
    uint32_t d;
    asm("prmt.b32 %0, %1, %2, 0x7632;" : "=r"(d) : "r"(a), "r"(b));
    return d;
}
__device__ __forceinline__ uint32_t bf16x2_rn(float h, float l) {
    uint32_t d;
    asm("cvt.rn.satfinite.bf16x2.f32 %0, %1, %2;" : "=r"(d) : "f"(h), "f"(l));
    return d;
}
__device__ __forceinline__ uint32_t f16x2_rn(float h, float l) {
    uint32_t d;
    asm("cvt.rn.f16x2.f32 %0, %1, %2;" : "=r"(d) : "f"(h), "f"(l));
    return d;
}

// ---------------------------------------------------------------------------
// Splits
// ---------------------------------------------------------------------------
__global__ __launch_bounds__(256)
void split_x(const float* __restrict__ src, __half* __restrict__ h, int n4)
{
    int i = blockIdx.x * blockDim.x + threadIdx.x;
    if (i >= n4) return;
    float4 v = reinterpret_cast<const float4*>(src)[i];
    uint2 hu;
    hu.x = f16x2_rn(v.y, v.x);
    hu.y = f16x2_rn(v.w, v.z);
    reinterpret_cast<uint2*>(h)[i] = hu;
}

struct WSplit { const float* src[4]; };

__global__ __launch_bounds__(256)
void split_w(WSplit ws, __half* __restrict__ hBase, __half* __restrict__ lBase,
             int n4)
{
    const int w = blockIdx.y;
    const float* src = ws.src[w];
    __half* hi = hBase + (size_t)w * H_ * H_;
    __half* lo = lBase + (size_t)w * H_ * H_;
    int i = blockIdx.x * blockDim.x + threadIdx.x;
    if (i >= n4) return;
    float4 v = reinterpret_cast<const float4*>(src)[i];
    float w0 = v.x * WSC, w1 = v.y * WSC, w2 = v.z * WSC, w3 = v.w * WSC;
    float h0 = __half2float(__float2half_rn(w0));
    float h1 = __half2float(__float2half_rn(w1));
    float h2 = __half2float(__float2half_rn(w2));
    float h3 = __half2float(__float2half_rn(w3));
    uint2 hu, lu;
    hu.x = f16x2_rn(w1, w0);
    hu.y = f16x2_rn(w3, w2);
    lu.x = f16x2_rn(w1 - h1, w0 - h0);
    lu.y = f16x2_rn(w3 - h3, w2 - h2);
    reinterpret_cast<uint2*>(hi)[i] = hu;
    reinterpret_cast<uint2*>(lo)[i] = lu;
}

// ---------------------------------------------------------------------------
// fp16x2 GEMM (2 passes): C = (A @ (32W)^T)/32 + bias, then *scale.
// Tiles per K-chunk: A_h, W_h, W_l (fp16). CTA 128x128, 8 warps 64x32.
// MODE 1: fused QKV (blockIdx.z), bf16 hi/lo scatter [B*NH,S,HD].
// MODE 0: fp32 out [M,H].
// ---------------------------------------------------------------------------
constexpr int RPB = 40;
constexpr int TB  = 128 * RPB * 2;      // 10240
constexpr int O_AH = 0, O_WH = TB, O_WL = 2 * TB;
constexpr int GBUF = 3 * TB;            // 30720
constexpr int GEMM_SMEM = 2 * GBUF;     // 61440

struct G3 {
    const float* bias[3];
    __nv_bfloat16* ohi[3];
    __nv_bfloat16* olo[3];
    float scale[3];
};

template <int MODE>
__global__ __launch_bounds__(256)
void gemm2(const __half* __restrict__ Ah,
           const __half* __restrict__ WhB, const __half* __restrict__ WlB,
           G3 g, float* __restrict__ Cf)
{
    extern __shared__ char smem[];
    const uint32_t sb = smem_u32(smem);
    const int tid = threadIdx.x, wid = tid >> 5, lane = tid & 31;
    const int z = (MODE == 1) ? blockIdx.z : 0;
    const int m0 = blockIdx.y * 128, n0 = blockIdx.x * 128;
    const int wm = (wid & 1) * 64, wn = (wid >> 1) * 32;
    const size_t WN = (size_t)H_ * H_;
    const __half* Wh = WhB + (size_t)z * WN;
    const __half* Wl = WlB + (size_t)z * WN;

    float acc[4][4][4];
    #pragma unroll
    for (int mi = 0; mi < 4; mi++)
        #pragma unroll
        for (int ni = 0; ni < 4; ni++)
            #pragma unroll
            for (int r = 0; r < 4; r++) acc[mi][ni][r] = 0.f;

    auto issue = [&](int c) {
        const int k0 = c * 32;
        const uint32_t bs = sb + (c & 1) * GBUF;
        #pragma unroll
        for (int t = 0; t < 2; t++) {
            int u = tid + t * 256;
            int row = u >> 2, seg = u & 3;
            uint32_t d = (row * RPB + seg * 8) * 2;
            size_t ga = (size_t)(m0 + row) * H_ + k0 + seg * 8;
            size_t gw = (size_t)(n0 + row) * H_ + k0 + seg * 8;
            cp_async16(bs + O_AH + d, Ah + ga);
            cp_async16(bs + O_WH + d, Wh + gw);
            cp_async16(bs + O_WL + d, Wl + gw);
        }
        CP_COMMIT();
    };

    issue(0);
    constexpr int NCH = H_ / 32;

    for (int c = 0; c < NCH; c++) {
        if (c + 1 < NCH) { issue(c + 1); CP_WAIT(1); }
        else             { CP_WAIT(0); }
        __syncthreads();
        const uint32_t bs = sb + (c & 1) * GBUF;

        #pragma unroll
        for (int ks = 0; ks < 2; ks++) {
            const int l = lane & 15;
            uint32_t af[4][4], bh[4][2], bl[4][2];
            #pragma unroll
            for (int mi = 0; mi < 4; mi++)
                ldmatrix_x4(af[mi], bs + O_AH +
                    ((wm + mi * 16 + l) * RPB + ks * 16 + (lane >> 4) * 8) * 2);
            #pragma unroll
            for (int ni = 0; ni < 4; ni++)
                ldmatrix_x2(bh[ni], bs + O_WH +
                    ((wn + ni * 8 + (l & 7)) * RPB + ks * 16 + (l >> 3) * 8) * 2);
            #pragma unroll
            for (int mi = 0; mi < 4; mi++)
                #pragma unroll
                for (int ni = 0; ni < 4; ni++)
                    mma_f16(acc[mi][ni], af[mi], bh[ni]);

            #pragma unroll
            for (int ni = 0; ni < 4; ni++)
                ldmatrix_x2(bl[ni], bs + O_WL +
                    ((wn + ni * 8 + (l & 7)) * RPB + ks * 16 + (l >> 3) * 8) * 2);
            #pragma unroll
            for (int mi = 0; mi < 4; mi++)
                #pragma unroll
                for (int ni = 0; ni < 4; ni++)
                    mma_f16(acc[mi][ni], af[mi], bl[ni]);
        }
        __syncthreads();
    }

    const float scale = g.scale[z];
    const float* bias = g.bias[z];
    const int frow = lane >> 2, fcol = (lane & 3) * 2;
    #pragma unroll
    for (int mi = 0; mi < 4; mi++) {
        #pragma unroll
        for (int ni = 0; ni < 4; ni++) {
            const int n = n0 + wn + ni * 8 + fcol;
            const float b0 = __ldg(&bias[n]);
            const float b1 = __ldg(&bias[n + 1]);
            #pragma unroll
            for (int half = 0; half < 2; half++) {
                const int m = m0 + wm + mi * 16 + frow + half * 8;
                float vx = (acc[mi][ni][half * 2 + 0] * INV_WSC + b0) * scale;
                float vy = (acc[mi][ni][half * 2 + 1] * INV_WSC + b1) * scale;
                if (MODE == 0) {
                    float2 val{vx, vy};
                    *reinterpret_cast<float2*>(&Cf[(size_t)m * H_ + n]) = val;
                } else {
                    const int b = m >> 11, s = m & 2047;
                    const int h = n >> 6, hd = n & 63;
                    size_t idx = (((size_t)(b * NH_ + h)) * S_ + s) * HD_ + hd;
                    uint32_t hi = prmt7632(__float_as_uint(vx), __float_as_uint(vy));
                    uint32_t lo = bf16x2_rn(vy - trunc_bf(vy), vx - trunc_bf(vx));
                    reinterpret_cast<uint32_t*>(g.ohi[z])[idx >> 1] = hi;
                    reinterpret_cast<uint32_t*>(g.olo[z])[idx >> 1] = lo;
                }
            }
        }
    }
}

// ---------------------------------------------------------------------------
// Flash attention (bf16x3, base-2 softmax), Q overlaid on KV buf1, 3 CTAs/SM.
// Epilogue emits fp16 output for the fp16x2 O-projection.
// ---------------------------------------------------------------------------
constexpr int RP = 72, TSZ = 64 * RP * 2;
constexpr int KVBUF = 4 * TSZ;
constexpr int ATTN_SMEM = 2 * KVBUF;    // 73728

__global__ __launch_bounds__(128, 3)
void attn_mma(const __nv_bfloat16* __restrict__ qhi, const __nv_bfloat16* __restrict__ qlo,
              const __nv_bfloat16* __restrict__ khi, const __nv_bfloat16* __restrict__ klo,
              const __nv_bfloat16* __restrict__ vhi, const __nv_bfloat16* __restrict__ vlo,
              __half* __restrict__ aout)
{
    extern __shared__ char smem[];
    const uint32_t sb = smem_u32(smem);
    const int tid = threadIdx.x, wid = tid >> 5, lane = tid & 31;
    const int qt = 31 - blockIdx.x;
    const int bh = blockIdx.y;
    const int q0 = qt * 64;
    const size_t boff = (size_t)bh * S_ * HD_;
    const int wm = wid * 16;

    auto cp_tile = [&](uint32_t dst, const __nv_bfloat16* src) {
        #pragma unroll
        for (int t = 0; t < 4; t++) {
            int u = tid + t * 128, r = u >> 3, ch = u & 7;
            cp_async16(dst + (r * RP + ch * 8) * 2, src + (size_t)r * HD_ + ch * 8);
        }
    };
    const uint32_t qoff = sb + KVBUF;
    cp_tile(qoff,       qhi + boff + (size_t)q0 * HD_);
    cp_tile(qoff + TSZ, qlo + boff + (size_t)q0 * HD_);
    CP_COMMIT();
    auto issue = [&](int kt) {
        uint32_t kb = sb + (kt & 1) * KVBUF;
        const size_t o = boff + (size_t)kt * 64 * HD_;
        cp_tile(kb, khi + o);           cp_tile(kb + TSZ, klo + o);
        cp_tile(kb + 2 * TSZ, vhi + o); cp_tile(kb + 3 * TSZ, vlo + o);
        CP_COMMIT();
    };
    issue(0);
    CP_WAIT(1);
    __syncthreads();

    uint32_t qh[4][4], ql[4][4];
    #pragma unroll
    for (int ks = 0; ks < 4; ks++) {
        uint32_t a = qoff + ((wm + (lane & 15)) * RP + ks * 16 + (lane >> 4) * 8) * 2;
        ldmatrix_x4(qh[ks], a);
        ldmatrix_x4(ql[ks], a + TSZ);
    }
    __syncthreads();

    float o[8][4];
    #pragma unroll
    for (int j = 0; j < 8; j++)
        #pragma unroll
        for (int r = 0; r < 4; r++) o[j][r] = 0.f;
    float m_i[2] = {-1e30f, -1e30f}, l_i[2] = {0.f, 0.f};

    for (int kt = 0; kt <= qt; kt++) {
        if (kt < qt) { issue(kt + 1); CP_WAIT(1); }
        else         { CP_WAIT(0); }
        __syncthreads();
        const uint32_t kb = sb + (kt & 1) * KVBUF;

        float s[8][4];
        #pragma unroll
        for (int j = 0; j < 8; j++)
            #pragma unroll
            for (int r = 0; r < 4; r++) s[j][r] = 0.f;

        #pragma unroll
        for (int ks = 0; ks < 4; ks++) {
            #pragma unroll
            for (int j = 0; j < 8; j++) {
                uint32_t bh2[2], bl2[2];
                int l = lane & 15;
                uint32_t ka = kb + ((8 * j + (l & 7)) * RP + ks * 16 + (l >> 3) * 8) * 2;
                ldmatrix_x2(bh2, ka);
                ldmatrix_x2(bl2, ka + TSZ);
                mma_bf16(s[j], qh[ks], bh2);
                mma_bf16(s[j], ql[ks], bh2);
                mma_bf16(s[j], qh[ks], bl2);
            }
        }

        if (kt == qt) {
            const int r0 = wm + (lane >> 2);
            #pragma unroll
            for (int j = 0; j < 8; j++) {
                const int kc = 8 * j + 2 * (lane & 3);
                if (kc     > r0)     s[j][0] = -1e30f;
                if (kc + 1 > r0)     s[j][1] = -1e30f;
                if (kc     > r0 + 8) s[j][2] = -1e30f;
                if (kc + 1 > r0 + 8) s[j][3] = -1e30f;
            }
        }

        float mx0 = -1e30f, mx1 = -1e30f;
        #pragma unroll
        for (int j = 0; j < 8; j++) {
            mx0 = fmaxf(mx0, fmaxf(s[j][0], s[j][1]));
            mx1 = fmaxf(mx1, fmaxf(s[j][2], s[j][3]));
        }
        mx0 = fmaxf(mx0, __shfl_xor_sync(~0u, mx0, 1));
        mx0 = fmaxf(mx0, __shfl_xor_sync(~0u, mx0, 2));
        mx1 = fmaxf(mx1, __shfl_xor_sync(~0u, mx1, 1));
        mx1 = fmaxf(mx1, __shfl_xor_sync(~0u, mx1, 2));
        const float nm0 = fmaxf(m_i[0], mx0), nm1 = fmaxf(m_i[1], mx1);
        const float c0 = ex2f(m_i[0] - nm0), c1 = ex2f(m_i[1] - nm1);
        m_i[0] = nm0; m_i[1] = nm1;

        float rs0 = 0.f, rs1 = 0.f;
        #pragma unroll
        for (int j = 0; j < 8; j++) {
            s[j][0] = ex2f(s[j][0] - nm0);
            s[j][1] = ex2f(s[j][1] - nm0);
            s[j][2] = ex2f(s[j][2] - nm1);
            s[j][3] = ex2f(s[j][3] - nm1);
            rs0 += s[j][0] + s[j][1];
            rs1 += s[j][2] + s[j][3];
        }
        rs0 += __shfl_xor_sync(~0u, rs0, 1);
        rs0 += __shfl_xor_sync(~0u, rs0, 2);
        rs1 += __shfl_xor_sync(~0u, rs1, 1);
        rs1 += __shfl_xor_sync(~0u, rs1, 2);
        l_i[0] = l_i[0] * c0 + rs0;
        l_i[1] = l_i[1] * c1 + rs1;
        #pragma unroll
        for (int j = 0; j < 8; j++) {
            o[j][0] *= c0; o[j][1] *= c0;
            o[j][2] *= c1; o[j][3] *= c1;
        }

        uint32_t ph[4][4], pl[4][4];
        #pragma unroll
        for (int k2 = 0; k2 < 4; k2++) {
            #pragma unroll
            for (int half = 0; half < 2; half++) {
                const int j = 2 * k2 + half;
                ph[k2][half*2+0] = prmt7632(__float_as_uint(s[j][0]), __float_as_uint(s[j][1]));
                ph[k2][half*2+1] = prmt7632(__float_as_uint(s[j][2]), __float_as_uint(s[j][3]));
                pl[k2][half*2+0] = bf16x2_rn(s[j][1] - trunc_bf(s[j][1]),
                                             s[j][0] - trunc_bf(s[j][0]));
                pl[k2][half*2+1] = bf16x2_rn(s[j][3] - trunc_bf(s[j][3]),
                                             s[j][2] - trunc_bf(s[j][2]));
            }
        }

        const uint32_t vb = kb + 2 * TSZ;
        #pragma unroll
        for (int k2 = 0; k2 < 4; k2++) {
            #pragma unroll
            for (int j = 0; j < 8; j++) {
                uint32_t vh2[2], vl2[2];
                uint32_t va = vb + ((k2 * 16 + (lane & 15)) * RP + 8 * j) * 2;
                ldmatrix_x2_trans(vh2, va);
                ldmatrix_x2_trans(vl2, va + TSZ);
                mma_bf16(o[j], ph[k2], vh2);
                mma_bf16(o[j], pl[k2], vh2);
                mma_bf16(o[j], ph[k2], vl2);
            }
        }
        __syncthreads();
    }

    const float inv0 = 1.f / l_i[0], inv1 = 1.f / l_i[1];
    const int b = bh >> 4, h = bh & 15;
    const int r0 = q0 + wm + (lane >> 2);
    const size_t base0 = ((size_t)(b * S_) + r0) * H_ + h * 64;
    const size_t base1 = base0 + (size_t)8 * H_;
    #pragma unroll
    for (int j = 0; j < 8; j++) {
        const int c = 8 * j + 2 * (lane & 3);
        reinterpret_cast<uint32_t*>(aout)[(base0 + c) >> 1] =
            f16x2_rn(o[j][1] * inv0, o[j][0] * inv0);
        reinterpret_cast<uint32_t*>(aout)[(base1 + c) >> 1] =
            f16x2_rn(o[j][3] * inv1, o[j][2] * inv1);
    }
}

// ---------------------------------------------------------------------------
extern "C" void kernel_launch(void* const* d_in, const int* in_sizes, int n_in,
                              void* d_out, int out_size)
{
    const float* x  = (const float*)d_in[0];
    const float* Wq = (const float*)d_in[1];
    const float* bq = (const float*)d_in[2];
    const float* Wk = (const float*)d_in[3];
    const float* bk = (const float*)d_in[4];
    const float* Wv = (const float*)d_in[5];
    const float* bv = (const float*)d_in[6];
    const float* Wo = (const float*)d_in[7];
    const float* bo = (const float*)d_in[8];
    float* out = (float*)d_out;

    __half *xh, *wh, *wl, *ah;
    __nv_bfloat16 *q_hi, *q_lo, *k_hi, *k_lo, *v_hi, *v_lo;
    cudaGetSymbolAddress((void**)&xh, g_xh);
    cudaGetSymbolAddress((void**)&wh, g_wh);
    cudaGetSymbolAddress((void**)&wl, g_wl);
    cudaGetSymbolAddress((void**)&ah, g_ah);
    cudaGetSymbolAddress((void**)&q_hi, g_qhi);
    cudaGetSymbolAddress((void**)&q_lo, g_qlo);
    cudaGetSymbolAddress((void**)&k_hi, g_khi);
    cudaGetSymbolAddress((void**)&k_lo, g_klo);
    cudaGetSymbolAddress((void**)&v_hi, g_vhi);
    cudaGetSymbolAddress((void**)&v_lo, g_vlo);

    cudaFuncSetAttribute(gemm2<0>, cudaFuncAttributeMaxDynamicSharedMemorySize, GEMM_SMEM);
    cudaFuncSetAttribute(gemm2<1>, cudaFuncAttributeMaxDynamicSharedMemorySize, GEMM_SMEM);
    cudaFuncSetAttribute(attn_mma, cudaFuncAttributeMaxDynamicSharedMemorySize, ATTN_SMEM);

    const size_t WN = (size_t)H_ * H_;

    {
        int n4 = (M_ * H_) / 4;
        split_x<<<(n4 + 255) / 256, 256>>>(x, xh, n4);
        WSplit ws;
        ws.src[0] = Wq; ws.src[1] = Wk; ws.src[2] = Wv; ws.src[3] = Wo;
        int w4 = (H_ * H_) / 4;
        dim3 wg((w4 + 255) / 256, 4);
        split_w<<<wg, 256>>>(ws, wh, wl, w4);
    }

    G3 g;
    g.bias[0] = bq;  g.bias[1] = bk;  g.bias[2] = bv;
    g.ohi[0] = q_hi; g.ohi[1] = k_hi; g.ohi[2] = v_hi;
    g.olo[0] = q_lo; g.olo[1] = k_lo; g.olo[2] = v_lo;
    g.scale[0] = SCALE_Q; g.scale[1] = 1.0f; g.scale[2] = 1.0f;
    dim3 gq(H_ / 128, M_ / 128, 3);
    gemm2<1><<<gq, 256, GEMM_SMEM>>>(xh, wh, wl, g, nullptr);

    dim3 ag(S_ / 64, B_ * NH_);
    attn_mma<<<ag, 128, ATTN_SMEM>>>(q_hi, q_lo, k_hi, k_lo, v_hi, v_lo, ah);

    G3 go;
    go.bias[0] = bo; go.bias[1] = bo; go.bias[2] = bo;
    go.ohi[0] = nullptr; go.ohi[1] = nullptr; go.ohi[2] = nullptr;
    go.olo[0] = nullptr; go.olo[1] = nullptr; go.olo[2] = nullptr;
    go.scale[0] = 1.0f; go.scale[1] = 1.0f; go.scale[2] = 1.0f;
    dim3 gg(H_ / 128, M_ / 128, 1);
    gemm2<0><<<gg, 256, GEMM_SMEM>>>(ah, wh + 3 * WN, wl + 3 * WN, go, out);
}

// round 10
// speedup vs baseline: 2.8476x; 1.0952x over previous
#include <cuda_runtime.h>
#include <cuda_bf16.h>
#include <cuda_fp16.h>
#include <cstdint>
#include <cstddef>

constexpr int B_ = 4, S_ = 2048, H_ = 1024, NH_ = 16, HD_ = 64;
constexpr int M_ = B_ * S_;
constexpr float SCALE_Q = 0.18033688011112042f;  // 0.125 * log2(e)
constexpr float WSC = 32.0f, INV_WSC = 1.0f / 32.0f;

// Scratch
__device__ __half g_xh[(size_t)M_ * H_];      // fp16(x)
__device__ __half g_wh[4 * (size_t)H_ * H_];  // fp16(32*W)
__device__ __half g_wl[4 * (size_t)H_ * H_];  // fp16 residual
__device__ __half g_q16[(size_t)M_ * H_];     // Q fp16 (hi only used)
__device__ __half g_q16l[(size_t)M_ * H_];
__device__ __half g_k16h[(size_t)M_ * H_];
__device__ __half g_k16l[(size_t)M_ * H_];
__device__ __half g_v16h[(size_t)M_ * H_];
__device__ __half g_v16l[(size_t)M_ * H_];
__device__ __half g_ah[(size_t)M_ * H_];      // attention out fp16

__device__ __forceinline__ uint32_t smem_u32(const void* p) {
    uint32_t a;
    asm("{ .reg .u64 t; cvta.to.shared.u64 t, %1; cvt.u32.u64 %0, t; }"
        : "=r"(a) : "l"(p));
    return a;
}
__device__ __forceinline__ void cp_async16(uint32_t dst, const void* src) {
    asm volatile("cp.async.cg.shared.global [%0], [%1], 16;"
                 :: "r"(dst), "l"(src) : "memory");
}
#define CP_COMMIT() asm volatile("cp.async.commit_group;" ::: "memory")
#define CP_WAIT(n)  asm volatile("cp.async.wait_group %0;" :: "n"(n) : "memory")

__device__ __forceinline__ void ldmatrix_x4(uint32_t* r, uint32_t a) {
    asm volatile("ldmatrix.sync.aligned.m8n8.x4.shared.b16 {%0,%1,%2,%3}, [%4];"
                 : "=r"(r[0]), "=r"(r[1]), "=r"(r[2]), "=r"(r[3]) : "r"(a));
}
__device__ __forceinline__ void ldmatrix_x2(uint32_t* r, uint32_t a) {
    asm volatile("ldmatrix.sync.aligned.m8n8.x2.shared.b16 {%0,%1}, [%2];"
                 : "=r"(r[0]), "=r"(r[1]) : "r"(a));
}
__device__ __forceinline__ void ldmatrix_x2_trans(uint32_t* r, uint32_t a) {
    asm volatile("ldmatrix.sync.aligned.m8n8.x2.trans.shared.b16 {%0,%1}, [%2];"
                 : "=r"(r[0]), "=r"(r[1]) : "r"(a));
}
__device__ __forceinline__ void mma_f16(float* c, const uint32_t* a,
                                        const uint32_t* b) {
    asm volatile(
        "mma.sync.aligned.m16n8k16.row.col.f32.f16.f16.f32 "
        "{%0,%1,%2,%3}, {%4,%5,%6,%7}, {%8,%9}, {%0,%1,%2,%3};"
        : "+f"(c[0]), "+f"(c[1]), "+f"(c[2]), "+f"(c[3])
        : "r"(a[0]), "r"(a[1]), "r"(a[2]), "r"(a[3]), "r"(b[0]), "r"(b[1]));
}
__device__ __forceinline__ float ex2f(float x) {
    float y; asm("ex2.approx.ftz.f32 %0, %1;" : "=f"(y) : "f"(x)); return y;
}
__device__ __forceinline__ uint32_t f16x2_rn(float h, float l) {
    uint32_t d;
    asm("cvt.rn.f16x2.f32 %0, %1, %2;" : "=r"(d) : "f"(h), "f"(l));
    return d;
}
__device__ __forceinline__ float h2f_lo(uint32_t p) {
    __half h = __ushort_as_half((uint16_t)(p & 0xFFFF));
    return __half2float(h);
}

// ---------------------------------------------------------------------------
// Splits
// ---------------------------------------------------------------------------
__global__ __launch_bounds__(256)
void split_x(const float* __restrict__ src, __half* __restrict__ h, int n4)
{
    int i = blockIdx.x * blockDim.x + threadIdx.x;
    if (i >= n4) return;
    float4 v = reinterpret_cast<const float4*>(src)[i];
    uint2 hu;
    hu.x = f16x2_rn(v.y, v.x);
    hu.y = f16x2_rn(v.w, v.z);
    reinterpret_cast<uint2*>(h)[i] = hu;
}

struct WSplit { const float* src[4]; };

__global__ __launch_bounds__(256)
void split_w(WSplit ws, __half* __restrict__ hBase, __half* __restrict__ lBase,
             int n4)
{
    const int w = blockIdx.y;
    const float* src = ws.src[w];
    __half* hi = hBase + (size_t)w * H_ * H_;
    __half* lo = lBase + (size_t)w * H_ * H_;
    int i = blockIdx.x * blockDim.x + threadIdx.x;
    if (i >= n4) return;
    float4 v = reinterpret_cast<const float4*>(src)[i];
    float w0 = v.x * WSC, w1 = v.y * WSC, w2 = v.z * WSC, w3 = v.w * WSC;
    float h0 = __half2float(__float2half_rn(w0));
    float h1 = __half2float(__float2half_rn(w1));
    float h2 = __half2float(__float2half_rn(w2));
    float h3 = __half2float(__float2half_rn(w3));
    uint2 hu, lu;
    hu.x = f16x2_rn(w1, w0);
    hu.y = f16x2_rn(w3, w2);
    lu.x = f16x2_rn(w1 - h1, w0 - h0);
    lu.y = f16x2_rn(w3 - h3, w2 - h2);
    reinterpret_cast<uint2*>(hi)[i] = hu;
    reinterpret_cast<uint2*>(lo)[i] = lu;
}

// ---------------------------------------------------------------------------
// fp16x2 GEMM (2 passes): C = (A @ (32W)^T)/32 + bias, then *scale.
// MODE 1: fused QKV (blockIdx.z), fp16 hi/lo scatter [B*NH,S,HD].
// MODE 0: fp32 out [M,H].
// ---------------------------------------------------------------------------
constexpr int RPB = 40;
constexpr int TB  = 128 * RPB * 2;      // 10240
constexpr int O_AH = 0, O_WH = TB, O_WL = 2 * TB;
constexpr int GBUF = 3 * TB;            // 30720
constexpr int GEMM_SMEM = 2 * GBUF;     // 61440

struct G3 {
    const float* bias[3];
    __half* ohi[3];
    __half* olo[3];
    float scale[3];
};

template <int MODE>
__global__ __launch_bounds__(256)
void gemm2(const __half* __restrict__ Ah,
           const __half* __restrict__ WhB, const __half* __restrict__ WlB,
           G3 g, float* __restrict__ Cf)
{
    extern __shared__ char smem[];
    const uint32_t sb = smem_u32(smem);
    const int tid = threadIdx.x, wid = tid >> 5, lane = tid & 31;
    const int z = (MODE == 1) ? blockIdx.z : 0;
    const int m0 = blockIdx.y * 128, n0 = blockIdx.x * 128;
    const int wm = (wid & 1) * 64, wn = (wid >> 1) * 32;
    const size_t WN = (size_t)H_ * H_;
    const __half* Wh = WhB + (size_t)z * WN;
    const __half* Wl = WlB + (size_t)z * WN;

    float acc[4][4][4];
    #pragma unroll
    for (int mi = 0; mi < 4; mi++)
        #pragma unroll
        for (int ni = 0; ni < 4; ni++)
            #pragma unroll
            for (int r = 0; r < 4; r++) acc[mi][ni][r] = 0.f;

    auto issue = [&](int c) {
        const int k0 = c * 32;
        const uint32_t bs = sb + (c & 1) * GBUF;
        #pragma unroll
        for (int t = 0; t < 2; t++) {
            int u = tid + t * 256;
            int row = u >> 2, seg = u & 3;
            uint32_t d = (row * RPB + seg * 8) * 2;
            size_t ga = (size_t)(m0 + row) * H_ + k0 + seg * 8;
            size_t gw = (size_t)(n0 + row) * H_ + k0 + seg * 8;
            cp_async16(bs + O_AH + d, Ah + ga);
            cp_async16(bs + O_WH + d, Wh + gw);
            cp_async16(bs + O_WL + d, Wl + gw);
        }
        CP_COMMIT();
    };

    issue(0);
    constexpr int NCH = H_ / 32;

    for (int c = 0; c < NCH; c++) {
        if (c + 1 < NCH) { issue(c + 1); CP_WAIT(1); }
        else             { CP_WAIT(0); }
        __syncthreads();
        const uint32_t bs = sb + (c & 1) * GBUF;

        #pragma unroll
        for (int ks = 0; ks < 2; ks++) {
            const int l = lane & 15;
            uint32_t af[4][4], bh[4][2], bl[4][2];
            #pragma unroll
            for (int mi = 0; mi < 4; mi++)
                ldmatrix_x4(af[mi], bs + O_AH +
                    ((wm + mi * 16 + l) * RPB + ks * 16 + (lane >> 4) * 8) * 2);
            #pragma unroll
            for (int ni = 0; ni < 4; ni++)
                ldmatrix_x2(bh[ni], bs + O_WH +
                    ((wn + ni * 8 + (l & 7)) * RPB + ks * 16 + (l >> 3) * 8) * 2);
            #pragma unroll
            for (int mi = 0; mi < 4; mi++)
                #pragma unroll
                for (int ni = 0; ni < 4; ni++)
                    mma_f16(acc[mi][ni], af[mi], bh[ni]);

            #pragma unroll
            for (int ni = 0; ni < 4; ni++)
                ldmatrix_x2(bl[ni], bs + O_WL +
                    ((wn + ni * 8 + (l & 7)) * RPB + ks * 16 + (l >> 3) * 8) * 2);
            #pragma unroll
            for (int mi = 0; mi < 4; mi++)
                #pragma unroll
                for (int ni = 0; ni < 4; ni++)
                    mma_f16(acc[mi][ni], af[mi], bl[ni]);
        }
        __syncthreads();
    }

    const float scale = g.scale[z];
    const float* bias = g.bias[z];
    const int frow = lane >> 2, fcol = (lane & 3) * 2;
    #pragma unroll
    for (int mi = 0; mi < 4; mi++) {
        #pragma unroll
        for (int ni = 0; ni < 4; ni++) {
            const int n = n0 + wn + ni * 8 + fcol;
            const float b0 = __ldg(&bias[n]);
            const float b1 = __ldg(&bias[n + 1]);
            #pragma unroll
            for (int half = 0; half < 2; half++) {
                const int m = m0 + wm + mi * 16 + frow + half * 8;
                float vx = (acc[mi][ni][half * 2 + 0] * INV_WSC + b0) * scale;
                float vy = (acc[mi][ni][half * 2 + 1] * INV_WSC + b1) * scale;
                if (MODE == 0) {
                    float2 val{vx, vy};
                    *reinterpret_cast<float2*>(&Cf[(size_t)m * H_ + n]) = val;
                } else {
                    const int b = m >> 11, s = m & 2047;
                    const int h = n >> 6, hd = n & 63;
                    size_t idx = (((size_t)(b * NH_ + h)) * S_ + s) * HD_ + hd;
                    uint32_t hi = f16x2_rn(vy, vx);
                    float hx = h2f_lo(hi), hy = h2f_lo(hi >> 16);
                    uint32_t lo = f16x2_rn(vy - hy, vx - hx);
                    reinterpret_cast<uint32_t*>(g.ohi[z])[idx >> 1] = hi;
                    reinterpret_cast<uint32_t*>(g.olo[z])[idx >> 1] = lo;
                }
            }
        }
    }
}

// ---------------------------------------------------------------------------
// Flash attention, fp16x2 (QK: q*kh + q*kl; PV: p*vh + p*vl), base-2 softmax.
// Q overlaid on KV buffer 1. 3 CTAs/SM.
// ---------------------------------------------------------------------------
constexpr int RP = 72, TSZ = 64 * RP * 2;
constexpr int KVBUF = 4 * TSZ;
constexpr int ATTN_SMEM = 2 * KVBUF;    // 73728

__global__ __launch_bounds__(128, 3)
void attn_mma(const __half* __restrict__ q16,
              const __half* __restrict__ k16h, const __half* __restrict__ k16l,
              const __half* __restrict__ v16h, const __half* __restrict__ v16l,
              __half* __restrict__ aout)
{
    extern __shared__ char smem[];
    const uint32_t sb = smem_u32(smem);
    const int tid = threadIdx.x, wid = tid >> 5, lane = tid & 31;
    const int qt = 31 - blockIdx.x;
    const int bh = blockIdx.y;
    const int q0 = qt * 64;
    const size_t boff = (size_t)bh * S_ * HD_;
    const int wm = wid * 16;

    auto cp_tile = [&](uint32_t dst, const __half* src) {
        #pragma unroll
        for (int t = 0; t < 4; t++) {
            int u = tid + t * 128, r = u >> 3, ch = u & 7;
            cp_async16(dst + (r * RP + ch * 8) * 2, src + (size_t)r * HD_ + ch * 8);
        }
    };
    const uint32_t qoff = sb + KVBUF;
    cp_tile(qoff, q16 + boff + (size_t)q0 * HD_);
    CP_COMMIT();
    auto issue = [&](int kt) {
        uint32_t kb = sb + (kt & 1) * KVBUF;
        const size_t o = boff + (size_t)kt * 64 * HD_;
        cp_tile(kb, k16h + o);           cp_tile(kb + TSZ, k16l + o);
        cp_tile(kb + 2 * TSZ, v16h + o); cp_tile(kb + 3 * TSZ, v16l + o);
        CP_COMMIT();
    };
    issue(0);
    CP_WAIT(1);        // Q complete
    __syncthreads();

    uint32_t qh[4][4];
    #pragma unroll
    for (int ks = 0; ks < 4; ks++) {
        uint32_t a = qoff + ((wm + (lane & 15)) * RP + ks * 16 + (lane >> 4) * 8) * 2;
        ldmatrix_x4(qh[ks], a);
    }
    __syncthreads();   // Q fragments loaded before issue(1) overwrites region

    float o[8][4];
    #pragma unroll
    for (int j = 0; j < 8; j++)
        #pragma unroll
        for (int r = 0; r < 4; r++) o[j][r] = 0.f;
    float m_i[2] = {-1e30f, -1e30f}, l_i[2] = {0.f, 0.f};

    for (int kt = 0; kt <= qt; kt++) {
        if (kt < qt) { issue(kt + 1); CP_WAIT(1); }
        else         { CP_WAIT(0); }
        __syncthreads();
        const uint32_t kb = sb + (kt & 1) * KVBUF;

        float s[8][4];
        #pragma unroll
        for (int j = 0; j < 8; j++)
            #pragma unroll
            for (int r = 0; r < 4; r++) s[j][r] = 0.f;

        #pragma unroll
        for (int ks = 0; ks < 4; ks++) {
            #pragma unroll
            for (int j = 0; j < 8; j++) {
                uint32_t bh2[2], bl2[2];
                int l = lane & 15;
                uint32_t ka = kb + ((8 * j + (l & 7)) * RP + ks * 16 + (l >> 3) * 8) * 2;
                ldmatrix_x2(bh2, ka);
                ldmatrix_x2(bl2, ka + TSZ);
                mma_f16(s[j], qh[ks], bh2);
                mma_f16(s[j], qh[ks], bl2);
            }
        }

        if (kt == qt) {
            const int r0 = wm + (lane >> 2);
            #pragma unroll
            for (int j = 0; j < 8; j++) {
                const int kc = 8 * j + 2 * (lane & 3);
                if (kc     > r0)     s[j][0] = -1e30f;
                if (kc + 1 > r0)     s[j][1] = -1e30f;
                if (kc     > r0 + 8) s[j][2] = -1e30f;
                if (kc + 1 > r0 + 8) s[j][3] = -1e30f;
            }
        }

        float mx0 = -1e30f, mx1 = -1e30f;
        #pragma unroll
        for (int j = 0; j < 8; j++) {
            mx0 = fmaxf(mx0, fmaxf(s[j][0], s[j][1]));
            mx1 = fmaxf(mx1, fmaxf(s[j][2], s[j][3]));
        }
        mx0 = fmaxf(mx0, __shfl_xor_sync(~0u, mx0, 1));
        mx0 = fmaxf(mx0, __shfl_xor_sync(~0u, mx0, 2));
        mx1 = fmaxf(mx1, __shfl_xor_sync(~0u, mx1, 1));
        mx1 = fmaxf(mx1, __shfl_xor_sync(~0u, mx1, 2));
        const float nm0 = fmaxf(m_i[0], mx0), nm1 = fmaxf(m_i[1], mx1);
        const float c0 = ex2f(m_i[0] - nm0), c1 = ex2f(m_i[1] - nm1);
        m_i[0] = nm0; m_i[1] = nm1;

        float rs0 = 0.f, rs1 = 0.f;
        #pragma unroll
        for (int j = 0; j < 8; j++) {
            s[j][0] = ex2f(s[j][0] - nm0);
            s[j][1] = ex2f(s[j][1] - nm0);
            s[j][2] = ex2f(s[j][2] - nm1);
            s[j][3] = ex2f(s[j][3] - nm1);
            rs0 += s[j][0] + s[j][1];
            rs1 += s[j][2] + s[j][3];
        }
        rs0 += __shfl_xor_sync(~0u, rs0, 1);
        rs0 += __shfl_xor_sync(~0u, rs0, 2);
        rs1 += __shfl_xor_sync(~0u, rs1, 1);
        rs1 += __shfl_xor_sync(~0u, rs1, 2);
        l_i[0] = l_i[0] * c0 + rs0;
        l_i[1] = l_i[1] * c1 + rs1;
        #pragma unroll
        for (int j = 0; j < 8; j++) {
            o[j][0] *= c0; o[j][1] *= c0;
            o[j][2] *= c1; o[j][3] *= c1;
        }

        // pack P (fp16 single precision suffices for probabilities)
        uint32_t ph[4][4];
        #pragma unroll
        for (int k2 = 0; k2 < 4; k2++) {
            #pragma unroll
            for (int half = 0; half < 2; half++) {
                const int j = 2 * k2 + half;
                ph[k2][half * 2 + 0] = f16x2_rn(s[j][1], s[j][0]);
                ph[k2][half * 2 + 1] = f16x2_rn(s[j][3], s[j][2]);
            }
        }

        const uint32_t vb = kb + 2 * TSZ;
        #pragma unroll
        for (int k2 = 0; k2 < 4; k2++) {
            #pragma unroll
            for (int j = 0; j < 8; j++) {
                uint32_t vh2[2], vl2[2];
                uint32_t va = vb + ((k2 * 16 + (lane & 15)) * RP + 8 * j) * 2;
                ldmatrix_x2_trans(vh2, va);
                ldmatrix_x2_trans(vl2, va + TSZ);
                mma_f16(o[j], ph[k2], vh2);
                mma_f16(o[j], ph[k2], vl2);
            }
        }
        __syncthreads();
    }

    const float inv0 = 1.f / l_i[0], inv1 = 1.f / l_i[1];
    const int b = bh >> 4, h = bh & 15;
    const int r0 = q0 + wm + (lane >> 2);
    const size_t base0 = ((size_t)(b * S_) + r0) * H_ + h * 64;
    const size_t base1 = base0 + (size_t)8 * H_;
    #pragma unroll
    for (int j = 0; j < 8; j++) {
        const int c = 8 * j + 2 * (lane & 3);
        reinterpret_cast<uint32_t*>(aout)[(base0 + c) >> 1] =
            f16x2_rn(o[j][1] * inv0, o[j][0] * inv0);
        reinterpret_cast<uint32_t*>(aout)[(base1 + c) >> 1] =
            f16x2_rn(o[j][3] * inv1, o[j][2] * inv1);
    }
}

// ---------------------------------------------------------------------------
extern "C" void kernel_launch(void* const* d_in, const int* in_sizes, int n_in,
                              void* d_out, int out_size)
{
    const float* x  = (const float*)d_in[0];
    const float* Wq = (const float*)d_in[1];
    const float* bq = (const float*)d_in[2];
    const float* Wk = (const float*)d_in[3];
    const float* bk = (const float*)d_in[4];
    const float* Wv = (const float*)d_in[5];
    const float* bv = (const float*)d_in[6];
    const float* Wo = (const float*)d_in[7];
    const float* bo = (const float*)d_in[8];
    float* out = (float*)d_out;

    __half *xh, *wh, *wl, *ah;
    __half *q16, *q16l, *k16h, *k16l, *v16h, *v16l;
    cudaGetSymbolAddress((void**)&xh, g_xh);
    cudaGetSymbolAddress((void**)&wh, g_wh);
    cudaGetSymbolAddress((void**)&wl, g_wl);
    cudaGetSymbolAddress((void**)&ah, g_ah);
    cudaGetSymbolAddress((void**)&q16, g_q16);
    cudaGetSymbolAddress((void**)&q16l, g_q16l);
    cudaGetSymbolAddress((void**)&k16h, g_k16h);
    cudaGetSymbolAddress((void**)&k16l, g_k16l);
    cudaGetSymbolAddress((void**)&v16h, g_v16h);
    cudaGetSymbolAddress((void**)&v16l, g_v16l);

    cudaFuncSetAttribute(gemm2<0>, cudaFuncAttributeMaxDynamicSharedMemorySize, GEMM_SMEM);
    cudaFuncSetAttribute(gemm2<1>, cudaFuncAttributeMaxDynamicSharedMemorySize, GEMM_SMEM);
    cudaFuncSetAttribute(attn_mma, cudaFuncAttributeMaxDynamicSharedMemorySize, ATTN_SMEM);

    const size_t WN = (size_t)H_ * H_;

    {
        int n4 = (M_ * H_) / 4;
        split_x<<<(n4 + 255) / 256, 256>>>(x, xh, n4);
        WSplit ws;
        ws.src[0] = Wq; ws.src[1] = Wk; ws.src[2] = Wv; ws.src[3] = Wo;
        int w4 = (H_ * H_) / 4;
        dim3 wg((w4 + 255) / 256, 4);
        split_w<<<wg, 256>>>(ws, wh, wl, w4);
    }

    G3 g;
    g.bias[0] = bq;  g.bias[1] = bk;  g.bias[2] = bv;
    g.ohi[0] = q16;  g.ohi[1] = k16h; g.ohi[2] = v16h;
    g.olo[0] = q16l; g.olo[1] = k16l; g.olo[2] = v16l;
    g.scale[0] = SCALE_Q; g.scale[1] = 1.0f; g.scale[2] = 1.0f;
    dim3 gq(H_ / 128, M_ / 128, 3);
    gemm2<1><<<gq, 256, GEMM_SMEM>>>(xh, wh, wl, g, nullptr);

    dim3 ag(S_ / 64, B_ * NH_);
    attn_mma<<<ag, 128, ATTN_SMEM>>>(q16, k16h, k16l, v16h, v16l, ah);

    G3 go;
    go.bias[0] = bo; go.bias[1] = bo; go.bias[2] = bo;
    go.ohi[0] = nullptr; go.ohi[1] = nullptr; go.ohi[2] = nullptr;
    go.olo[0] = nullptr; go.olo[1] = nullptr; go.olo[2] = nullptr;
    go.scale[0] = 1.0f; go.scale[1] = 1.0f; go.scale[2] = 1.0f;
    dim3 gg(H_ / 128, M_ / 128, 1);
    gemm2<0><<<gg, 256, GEMM_SMEM>>>(ah, wh + 3 * WN, wl + 3 * WN, go, out);
}

// round 11
// speedup vs baseline: 3.2328x; 1.1353x over previous
#include <cuda_runtime.h>
#include <cuda_bf16.h>
#include <cuda_fp16.h>
#include <cstdint>
#include <cstddef>

constexpr int B_ = 4, S_ = 2048, H_ = 1024, NH_ = 16, HD_ = 64;
constexpr int M_ = B_ * S_;
constexpr float SCALE_Q = 0.18033688011112042f;  // 0.125 * log2(e)
constexpr float WSC = 32.0f, INV_WSC = 1.0f / 32.0f;

// Scratch
__device__ __half g_xh[(size_t)M_ * H_];      // fp16(x)
__device__ __half g_wh[4 * (size_t)H_ * H_];  // fp16(32*W)
__device__ __half g_wl[4 * (size_t)H_ * H_];  // fp16 residual
__device__ __half g_q16[(size_t)M_ * H_];     // Q fp16
__device__ __half g_q16l[(size_t)M_ * H_];    // (written, unused)
__device__ __half g_k16h[(size_t)M_ * H_];
__device__ __half g_k16l[(size_t)M_ * H_];
__device__ __half g_v16h[(size_t)M_ * H_];
__device__ __half g_v16l[(size_t)M_ * H_];    // (written, unused)
__device__ __half g_ah[(size_t)M_ * H_];      // attention out fp16

__device__ __forceinline__ uint32_t smem_u32(const void* p) {
    uint32_t a;
    asm("{ .reg .u64 t; cvta.to.shared.u64 t, %1; cvt.u32.u64 %0, t; }"
        : "=r"(a) : "l"(p));
    return a;
}
__device__ __forceinline__ void cp_async16(uint32_t dst, const void* src) {
    asm volatile("cp.async.cg.shared.global [%0], [%1], 16;"
                 :: "r"(dst), "l"(src) : "memory");
}
#define CP_COMMIT() asm volatile("cp.async.commit_group;" ::: "memory")
#define CP_WAIT(n)  asm volatile("cp.async.wait_group %0;" :: "n"(n) : "memory")

__device__ __forceinline__ void ldmatrix_x4(uint32_t* r, uint32_t a) {
    asm volatile("ldmatrix.sync.aligned.m8n8.x4.shared.b16 {%0,%1,%2,%3}, [%4];"
                 : "=r"(r[0]), "=r"(r[1]), "=r"(r[2]), "=r"(r[3]) : "r"(a));
}
__device__ __forceinline__ void ldmatrix_x2(uint32_t* r, uint32_t a) {
    asm volatile("ldmatrix.sync.aligned.m8n8.x2.shared.b16 {%0,%1}, [%2];"
                 : "=r"(r[0]), "=r"(r[1]) : "r"(a));
}
__device__ __forceinline__ void ldmatrix_x2_trans(uint32_t* r, uint32_t a) {
    asm volatile("ldmatrix.sync.aligned.m8n8.x2.trans.shared.b16 {%0,%1}, [%2];"
                 : "=r"(r[0]), "=r"(r[1]) : "r"(a));
}
__device__ __forceinline__ void mma_f16(float* c, const uint32_t* a,
                                        const uint32_t* b) {
    asm volatile(
        "mma.sync.aligned.m16n8k16.row.col.f32.f16.f16.f32 "
        "{%0,%1,%2,%3}, {%4,%5,%6,%7}, {%8,%9}, {%0,%1,%2,%3};"
        : "+f"(c[0]), "+f"(c[1]), "+f"(c[2]), "+f"(c[3])
        : "r"(a[0]), "r"(a[1]), "r"(a[2]), "r"(a[3]), "r"(b[0]), "r"(b[1]));
}
__device__ __forceinline__ float ex2f(float x) {
    float y; asm("ex2.approx.ftz.f32 %0, %1;" : "=f"(y) : "f"(x)); return y;
}
__device__ __forceinline__ uint32_t f16x2_rn(float h, float l) {
    uint32_t d;
    asm("cvt.rn.f16x2.f32 %0, %1, %2;" : "=r"(d) : "f"(h), "f"(l));
    return d;
}
__device__ __forceinline__ float h2f_lo(uint32_t p) {
    __half h = __ushort_as_half((uint16_t)(p & 0xFFFF));
    return __half2float(h);
}

// ---------------------------------------------------------------------------
// Splits
// ---------------------------------------------------------------------------
__global__ __launch_bounds__(256)
void split_x(const float* __restrict__ src, __half* __restrict__ h, int n4)
{
    int i = blockIdx.x * blockDim.x + threadIdx.x;
    if (i >= n4) return;
    float4 v = reinterpret_cast<const float4*>(src)[i];
    uint2 hu;
    hu.x = f16x2_rn(v.y, v.x);
    hu.y = f16x2_rn(v.w, v.z);
    reinterpret_cast<uint2*>(h)[i] = hu;
}

struct WSplit { const float* src[4]; };

__global__ __launch_bounds__(256)
void split_w(WSplit ws, __half* __restrict__ hBase, __half* __restrict__ lBase,
             int n4)
{
    const int w = blockIdx.y;
    const float* src = ws.src[w];
    __half* hi = hBase + (size_t)w * H_ * H_;
    __half* lo = lBase + (size_t)w * H_ * H_;
    int i = blockIdx.x * blockDim.x + threadIdx.x;
    if (i >= n4) return;
    float4 v = reinterpret_cast<const float4*>(src)[i];
    float w0 = v.x * WSC, w1 = v.y * WSC, w2 = v.z * WSC, w3 = v.w * WSC;
    float h0 = __half2float(__float2half_rn(w0));
    float h1 = __half2float(__float2half_rn(w1));
    float h2 = __half2float(__float2half_rn(w2));
    float h3 = __half2float(__float2half_rn(w3));
    uint2 hu, lu;
    hu.x = f16x2_rn(w1, w0);
    hu.y = f16x2_rn(w3, w2);
    lu.x = f16x2_rn(w1 - h1, w0 - h0);
    lu.y = f16x2_rn(w3 - h3, w2 - h2);
    reinterpret_cast<uint2*>(hi)[i] = hu;
    reinterpret_cast<uint2*>(lo)[i] = lu;
}

// ---------------------------------------------------------------------------
// fp16 GEMM: C = (A @ (32W)^T)/32 + bias, then *scale.
// Per-z pass count: 2 (w hi+lo) or 1 (w hi only).
// MODE 1: fused QKV (blockIdx.z; z=0,1 two-pass, z=2 one-pass),
//         fp16 hi/lo scatter [B*NH,S,HD].
// MODE 0: O-projection, ONE pass, fp32 out [M,H].
// ---------------------------------------------------------------------------
constexpr int RPB = 40;
constexpr int TB  = 128 * RPB * 2;      // 10240
constexpr int O_AH = 0, O_WH = TB, O_WL = 2 * TB;
constexpr int GBUF = 3 * TB;            // 30720
constexpr int GEMM_SMEM = 2 * GBUF;     // 61440

struct G3 {
    const float* bias[3];
    __half* ohi[3];
    __half* olo[3];
    float scale[3];
};

template <int MODE>
__global__ __launch_bounds__(256)
void gemm2(const __half* __restrict__ Ah,
           const __half* __restrict__ WhB, const __half* __restrict__ WlB,
           G3 g, float* __restrict__ Cf)
{
    extern __shared__ char smem[];
    const uint32_t sb = smem_u32(smem);
    const int tid = threadIdx.x, wid = tid >> 5, lane = tid & 31;
    const int z = (MODE == 1) ? blockIdx.z : 0;
    const bool two = (MODE == 1) && (z != 2);   // V-proj & O-proj: one pass
    const int m0 = blockIdx.y * 128, n0 = blockIdx.x * 128;
    const int wm = (wid & 1) * 64, wn = (wid >> 1) * 32;
    const size_t WN = (size_t)H_ * H_;
    const __half* Wh = WhB + (size_t)z * WN;
    const __half* Wl = WlB + (size_t)z * WN;

    float acc[4][4][4];
    #pragma unroll
    for (int mi = 0; mi < 4; mi++)
        #pragma unroll
        for (int ni = 0; ni < 4; ni++)
            #pragma unroll
            for (int r = 0; r < 4; r++) acc[mi][ni][r] = 0.f;

    auto issue = [&](int c) {
        const int k0 = c * 32;
        const uint32_t bs = sb + (c & 1) * GBUF;
        #pragma unroll
        for (int t = 0; t < 2; t++) {
            int u = tid + t * 256;
            int row = u >> 2, seg = u & 3;
            uint32_t d = (row * RPB + seg * 8) * 2;
            size_t ga = (size_t)(m0 + row) * H_ + k0 + seg * 8;
            size_t gw = (size_t)(n0 + row) * H_ + k0 + seg * 8;
            cp_async16(bs + O_AH + d, Ah + ga);
            cp_async16(bs + O_WH + d, Wh + gw);
            if (two) cp_async16(bs + O_WL + d, Wl + gw);
        }
        CP_COMMIT();
    };

    issue(0);
    constexpr int NCH = H_ / 32;

    for (int c = 0; c < NCH; c++) {
        if (c + 1 < NCH) { issue(c + 1); CP_WAIT(1); }
        else             { CP_WAIT(0); }
        __syncthreads();
        const uint32_t bs = sb + (c & 1) * GBUF;

        #pragma unroll
        for (int ks = 0; ks < 2; ks++) {
            const int l = lane & 15;
            uint32_t af[4][4], bh[4][2];
            #pragma unroll
            for (int mi = 0; mi < 4; mi++)
                ldmatrix_x4(af[mi], bs + O_AH +
                    ((wm + mi * 16 + l) * RPB + ks * 16 + (lane >> 4) * 8) * 2);
            #pragma unroll
            for (int ni = 0; ni < 4; ni++)
                ldmatrix_x2(bh[ni], bs + O_WH +
                    ((wn + ni * 8 + (l & 7)) * RPB + ks * 16 + (l >> 3) * 8) * 2);
            #pragma unroll
            for (int mi = 0; mi < 4; mi++)
                #pragma unroll
                for (int ni = 0; ni < 4; ni++)
                    mma_f16(acc[mi][ni], af[mi], bh[ni]);

            if (two) {
                uint32_t bl[4][2];
                #pragma unroll
                for (int ni = 0; ni < 4; ni++)
                    ldmatrix_x2(bl[ni], bs + O_WL +
                        ((wn + ni * 8 + (l & 7)) * RPB + ks * 16 + (l >> 3) * 8) * 2);
                #pragma unroll
                for (int mi = 0; mi < 4; mi++)
                    #pragma unroll
                    for (int ni = 0; ni < 4; ni++)
                        mma_f16(acc[mi][ni], af[mi], bl[ni]);
            }
        }
        __syncthreads();
    }

    const float scale = g.scale[z];
    const float* bias = g.bias[z];
    const int frow = lane >> 2, fcol = (lane & 3) * 2;
    #pragma unroll
    for (int mi = 0; mi < 4; mi++) {
        #pragma unroll
        for (int ni = 0; ni < 4; ni++) {
            const int n = n0 + wn + ni * 8 + fcol;
            const float b0 = __ldg(&bias[n]);
            const float b1 = __ldg(&bias[n + 1]);
            #pragma unroll
            for (int half = 0; half < 2; half++) {
                const int m = m0 + wm + mi * 16 + frow + half * 8;
                float vx = (acc[mi][ni][half * 2 + 0] * INV_WSC + b0) * scale;
                float vy = (acc[mi][ni][half * 2 + 1] * INV_WSC + b1) * scale;
                if (MODE == 0) {
                    float2 val{vx, vy};
                    *reinterpret_cast<float2*>(&Cf[(size_t)m * H_ + n]) = val;
                } else {
                    const int b = m >> 11, s = m & 2047;
                    const int h = n >> 6, hd = n & 63;
                    size_t idx = (((size_t)(b * NH_ + h)) * S_ + s) * HD_ + hd;
                    uint32_t hi = f16x2_rn(vy, vx);
                    float hx = h2f_lo(hi), hy = h2f_lo(hi >> 16);
                    uint32_t lo = f16x2_rn(vy - hy, vx - hx);
                    reinterpret_cast<uint32_t*>(g.ohi[z])[idx >> 1] = hi;
                    reinterpret_cast<uint32_t*>(g.olo[z])[idx >> 1] = lo;
                }
            }
        }
    }
}

// ---------------------------------------------------------------------------
// Flash attention: QK = q*(kh + kl) [2 passes], PV = p*vh [1 pass].
// KV buffer = 3 tiles (kh, kl, vh). Q overlaid on buffer 1. 3 CTAs/SM.
// ---------------------------------------------------------------------------
constexpr int RP = 72, TSZ = 64 * RP * 2;
constexpr int KVBUF = 3 * TSZ;
constexpr int ATTN_SMEM = 2 * KVBUF;    // 55296

__global__ __launch_bounds__(128, 3)
void attn_mma(const __half* __restrict__ q16,
              const __half* __restrict__ k16h, const __half* __restrict__ k16l,
              const __half* __restrict__ v16h,
              __half* __restrict__ aout)
{
    extern __shared__ char smem[];
    const uint32_t sb = smem_u32(smem);
    const int tid = threadIdx.x, wid = tid >> 5, lane = tid & 31;
    const int qt = 31 - blockIdx.x;
    const int bh = blockIdx.y;
    const int q0 = qt * 64;
    const size_t boff = (size_t)bh * S_ * HD_;
    const int wm = wid * 16;

    auto cp_tile = [&](uint32_t dst, const __half* src) {
        #pragma unroll
        for (int t = 0; t < 4; t++) {
            int u = tid + t * 128, r = u >> 3, ch = u & 7;
            cp_async16(dst + (r * RP + ch * 8) * 2, src + (size_t)r * HD_ + ch * 8);
        }
    };
    const uint32_t qoff = sb + KVBUF;     // Q overlays buffer 1
    cp_tile(qoff, q16 + boff + (size_t)q0 * HD_);
    CP_COMMIT();
    auto issue = [&](int kt) {
        uint32_t kb = sb + (kt & 1) * KVBUF;
        const size_t o = boff + (size_t)kt * 64 * HD_;
        cp_tile(kb, k16h + o);
        cp_tile(kb + TSZ, k16l + o);
        cp_tile(kb + 2 * TSZ, v16h + o);
        CP_COMMIT();
    };
    issue(0);
    CP_WAIT(1);        // Q complete
    __syncthreads();

    uint32_t qh[4][4];
    #pragma unroll
    for (int ks = 0; ks < 4; ks++) {
        uint32_t a = qoff + ((wm + (lane & 15)) * RP + ks * 16 + (lane >> 4) * 8) * 2;
        ldmatrix_x4(qh[ks], a);
    }
    __syncthreads();   // all warps done with Q before issue(1) overwrites it

    float o[8][4];
    #pragma unroll
    for (int j = 0; j < 8; j++)
        #pragma unroll
        for (int r = 0; r < 4; r++) o[j][r] = 0.f;
    float m_i[2] = {-1e30f, -1e30f}, l_i[2] = {0.f, 0.f};

    for (int kt = 0; kt <= qt; kt++) {
        if (kt < qt) { issue(kt + 1); CP_WAIT(1); }
        else         { CP_WAIT(0); }
        __syncthreads();
        const uint32_t kb = sb + (kt & 1) * KVBUF;

        float s[8][4];
        #pragma unroll
        for (int j = 0; j < 8; j++)
            #pragma unroll
            for (int r = 0; r < 4; r++) s[j][r] = 0.f;

        #pragma unroll
        for (int ks = 0; ks < 4; ks++) {
            #pragma unroll
            for (int j = 0; j < 8; j++) {
                uint32_t bh2[2], bl2[2];
                int l = lane & 15;
                uint32_t ka = kb + ((8 * j + (l & 7)) * RP + ks * 16 + (l >> 3) * 8) * 2;
                ldmatrix_x2(bh2, ka);
                ldmatrix_x2(bl2, ka + TSZ);
                mma_f16(s[j], qh[ks], bh2);
                mma_f16(s[j], qh[ks], bl2);
            }
        }

        if (kt == qt) {
            const int r0 = wm + (lane >> 2);
            #pragma unroll
            for (int j = 0; j < 8; j++) {
                const int kc = 8 * j + 2 * (lane & 3);
                if (kc     > r0)     s[j][0] = -1e30f;
                if (kc + 1 > r0)     s[j][1] = -1e30f;
                if (kc     > r0 + 8) s[j][2] = -1e30f;
                if (kc + 1 > r0 + 8) s[j][3] = -1e30f;
            }
        }

        float mx0 = -1e30f, mx1 = -1e30f;
        #pragma unroll
        for (int j = 0; j < 8; j++) {
            mx0 = fmaxf(mx0, fmaxf(s[j][0], s[j][1]));
            mx1 = fmaxf(mx1, fmaxf(s[j][2], s[j][3]));
        }
        mx0 = fmaxf(mx0, __shfl_xor_sync(~0u, mx0, 1));
        mx0 = fmaxf(mx0, __shfl_xor_sync(~0u, mx0, 2));
        mx1 = fmaxf(mx1, __shfl_xor_sync(~0u, mx1, 1));
        mx1 = fmaxf(mx1, __shfl_xor_sync(~0u, mx1, 2));
        const float nm0 = fmaxf(m_i[0], mx0), nm1 = fmaxf(m_i[1], mx1);
        const float c0 = ex2f(m_i[0] - nm0), c1 = ex2f(m_i[1] - nm1);
        m_i[0] = nm0; m_i[1] = nm1;

        float rs0 = 0.f, rs1 = 0.f;
        #pragma unroll
        for (int j = 0; j < 8; j++) {
            s[j][0] = ex2f(s[j][0] - nm0);
            s[j][1] = ex2f(s[j][1] - nm0);
            s[j][2] = ex2f(s[j][2] - nm1);
            s[j][3] = ex2f(s[j][3] - nm1);
            rs0 += s[j][0] + s[j][1];
            rs1 += s[j][2] + s[j][3];
        }
        rs0 += __shfl_xor_sync(~0u, rs0, 1);
        rs0 += __shfl_xor_sync(~0u, rs0, 2);
        rs1 += __shfl_xor_sync(~0u, rs1, 1);
        rs1 += __shfl_xor_sync(~0u, rs1, 2);
        l_i[0] = l_i[0] * c0 + rs0;
        l_i[1] = l_i[1] * c1 + rs1;
        #pragma unroll
        for (int j = 0; j < 8; j++) {
            o[j][0] *= c0; o[j][1] *= c0;
            o[j][2] *= c1; o[j][3] *= c1;
        }

        uint32_t ph[4][4];
        #pragma unroll
        for (int k2 = 0; k2 < 4; k2++) {
            #pragma unroll
            for (int half = 0; half < 2; half++) {
                const int j = 2 * k2 + half;
                ph[k2][half * 2 + 0] = f16x2_rn(s[j][1], s[j][0]);
                ph[k2][half * 2 + 1] = f16x2_rn(s[j][3], s[j][2]);
            }
        }

        const uint32_t vb = kb + 2 * TSZ;
        #pragma unroll
        for (int k2 = 0; k2 < 4; k2++) {
            #pragma unroll
            for (int j = 0; j < 8; j++) {
                uint32_t vh2[2];
                uint32_t va = vb + ((k2 * 16 + (lane & 15)) * RP + 8 * j) * 2;
                ldmatrix_x2_trans(vh2, va);
                mma_f16(o[j], ph[k2], vh2);
            }
        }
        __syncthreads();
    }

    const float inv0 = 1.f / l_i[0], inv1 = 1.f / l_i[1];
    const int b = bh >> 4, h = bh & 15;
    const int r0 = q0 + wm + (lane >> 2);
    const size_t base0 = ((size_t)(b * S_) + r0) * H_ + h * 64;
    const size_t base1 = base0 + (size_t)8 * H_;
    #pragma unroll
    for (int j = 0; j < 8; j++) {
        const int c = 8 * j + 2 * (lane & 3);
        reinterpret_cast<uint32_t*>(aout)[(base0 + c) >> 1] =
            f16x2_rn(o[j][1] * inv0, o[j][0] * inv0);
        reinterpret_cast<uint32_t*>(aout)[(base1 + c) >> 1] =
            f16x2_rn(o[j][3] * inv1, o[j][2] * inv1);
    }
}

// ---------------------------------------------------------------------------
extern "C" void kernel_launch(void* const* d_in, const int* in_sizes, int n_in,
                              void* d_out, int out_size)
{
    const float* x  = (const float*)d_in[0];
    const float* Wq = (const float*)d_in[1];
    const float* bq = (const float*)d_in[2];
    const float* Wk = (const float*)d_in[3];
    const float* bk = (const float*)d_in[4];
    const float* Wv = (const float*)d_in[5];
    const float* bv = (const float*)d_in[6];
    const float* Wo = (const float*)d_in[7];
    const float* bo = (const float*)d_in[8];
    float* out = (float*)d_out;

    __half *xh, *wh, *wl, *ah;
    __half *q16, *q16l, *k16h, *k16l, *v16h, *v16l;
    cudaGetSymbolAddress((void**)&xh, g_xh);
    cudaGetSymbolAddress((void**)&wh, g_wh);
    cudaGetSymbolAddress((void**)&wl, g_wl);
    cudaGetSymbolAddress((void**)&ah, g_ah);
    cudaGetSymbolAddress((void**)&q16, g_q16);
    cudaGetSymbolAddress((void**)&q16l, g_q16l);
    cudaGetSymbolAddress((void**)&k16h, g_k16h);
    cudaGetSymbolAddress((void**)&k16l, g_k16l);
    cudaGetSymbolAddress((void**)&v16h, g_v16h);
    cudaGetSymbolAddress((void**)&v16l, g_v16l);

    cudaFuncSetAttribute(gemm2<0>, cudaFuncAttributeMaxDynamicSharedMemorySize, GEMM_SMEM);
    cudaFuncSetAttribute(gemm2<1>, cudaFuncAttributeMaxDynamicSharedMemorySize, GEMM_SMEM);
    cudaFuncSetAttribute(attn_mma, cudaFuncAttributeMaxDynamicSharedMemorySize, ATTN_SMEM);

    const size_t WN = (size_t)H_ * H_;

    {
        int n4 = (M_ * H_) / 4;
        split_x<<<(n4 + 255) / 256, 256>>>(x, xh, n4);
        WSplit ws;
        ws.src[0] = Wq; ws.src[1] = Wk; ws.src[2] = Wv; ws.src[3] = Wo;
        int w4 = (H_ * H_) / 4;
        dim3 wg((w4 + 255) / 256, 4);
        split_w<<<wg, 256>>>(ws, wh, wl, w4);
    }

    G3 g;
    g.bias[0] = bq;  g.bias[1] = bk;  g.bias[2] = bv;
    g.ohi[0] = q16;  g.ohi[1] = k16h; g.ohi[2] = v16h;
    g.olo[0] = q16l; g.olo[1] = k16l; g.olo[2] = v16l;
    g.scale[0] = SCALE_Q; g.scale[1] = 1.0f; g.scale[2] = 1.0f;
    dim3 gq(H_ / 128, M_ / 128, 3);
    gemm2<1><<<gq, 256, GEMM_SMEM>>>(xh, wh, wl, g, nullptr);

    dim3 ag(S_ / 64, B_ * NH_);
    attn_mma<<<ag, 128, ATTN_SMEM>>>(q16, k16h, k16l, v16h, ah);

    G3 go;
    go.bias[0] = bo; go.bias[1] = bo; go.bias[2] = bo;
    go.ohi[0] = nullptr; go.ohi[1] = nullptr; go.ohi[2] = nullptr;
    go.olo[0] = nullptr; go.olo[1] = nullptr; go.olo[2] = nullptr;
    go.scale[0] = 1.0f; go.scale[1] = 1.0f; go.scale[2] = 1.0f;
    dim3 gg(H_ / 128, M_ / 128, 1);
    gemm2<0><<<gg, 256, GEMM_SMEM>>>(ah, wh + 3 * WN, wl + 3 * WN, go, out);
}

// round 12
// speedup vs baseline: 4.9904x; 1.5437x over previous
#include <cuda_runtime.h>
#include <cuda_fp16.h>
#include <cstdint>
#include <cstddef>

constexpr int B_ = 4, S_ = 2048, H_ = 1024, NH_ = 16, HD_ = 64;
constexpr int M_ = B_ * S_;
constexpr float SCALE_Q = 0.18033688011112042f;  // 0.125 * log2(e)
constexpr float WSC = 32.0f, INV_WSC = 1.0f / 32.0f;

// Scratch
__device__ __half g_xh[(size_t)M_ * H_];      // fp16(x)
__device__ __half g_wh[4 * (size_t)H_ * H_];  // fp16(32*W)
__device__ __half g_q16[(size_t)M_ * H_];     // [B*NH, S, HD]
__device__ __half g_k16[(size_t)M_ * H_];
__device__ __half g_v16[(size_t)M_ * H_];
__device__ __half g_ah[(size_t)M_ * H_];      // attention out [B,S,H]

__device__ __forceinline__ uint32_t smem_u32(const void* p) {
    uint32_t a;
    asm("{ .reg .u64 t; cvta.to.shared.u64 t, %1; cvt.u32.u64 %0, t; }"
        : "=r"(a) : "l"(p));
    return a;
}
__device__ __forceinline__ void cp_async16(uint32_t dst, const void* src) {
    asm volatile("cp.async.cg.shared.global [%0], [%1], 16;"
                 :: "r"(dst), "l"(src) : "memory");
}
#define CP_COMMIT() asm volatile("cp.async.commit_group;" ::: "memory")
#define CP_WAIT(n)  asm volatile("cp.async.wait_group %0;" :: "n"(n) : "memory")

__device__ __forceinline__ void ldmatrix_x4(uint32_t* r, uint32_t a) {
    asm volatile("ldmatrix.sync.aligned.m8n8.x4.shared.b16 {%0,%1,%2,%3}, [%4];"
                 : "=r"(r[0]), "=r"(r[1]), "=r"(r[2]), "=r"(r[3]) : "r"(a));
}
__device__ __forceinline__ void ldmatrix_x2(uint32_t* r, uint32_t a) {
    asm volatile("ldmatrix.sync.aligned.m8n8.x2.shared.b16 {%0,%1}, [%2];"
                 : "=r"(r[0]), "=r"(r[1]) : "r"(a));
}
__device__ __forceinline__ void ldmatrix_x2_trans(uint32_t* r, uint32_t a) {
    asm volatile("ldmatrix.sync.aligned.m8n8.x2.trans.shared.b16 {%0,%1}, [%2];"
                 : "=r"(r[0]), "=r"(r[1]) : "r"(a));
}
__device__ __forceinline__ void mma_f16(float* c, const uint32_t* a,
                                        const uint32_t* b) {
    asm volatile(
        "mma.sync.aligned.m16n8k16.row.col.f32.f16.f16.f32 "
        "{%0,%1,%2,%3}, {%4,%5,%6,%7}, {%8,%9}, {%0,%1,%2,%3};"
        : "+f"(c[0]), "+f"(c[1]), "+f"(c[2]), "+f"(c[3])
        : "r"(a[0]), "r"(a[1]), "r"(a[2]), "r"(a[3]), "r"(b[0]), "r"(b[1]));
}
__device__ __forceinline__ float ex2f(float x) {
    float y; asm("ex2.approx.ftz.f32 %0, %1;" : "=f"(y) : "f"(x)); return y;
}
__device__ __forceinline__ uint32_t f16x2_rn(float h, float l) {
    uint32_t d;
    asm("cvt.rn.f16x2.f32 %0, %1, %2;" : "=r"(d) : "f"(h), "f"(l));
    return d;
}

// ---------------------------------------------------------------------------
// Splits (x -> fp16; W -> fp16(32W))
// ---------------------------------------------------------------------------
__global__ __launch_bounds__(256)
void split_x(const float* __restrict__ src, __half* __restrict__ h, int n4)
{
    int i = blockIdx.x * blockDim.x + threadIdx.x;
    if (i >= n4) return;
    float4 v = reinterpret_cast<const float4*>(src)[i];
    uint2 hu;
    hu.x = f16x2_rn(v.y, v.x);
    hu.y = f16x2_rn(v.w, v.z);
    reinterpret_cast<uint2*>(h)[i] = hu;
}

struct WSplit { const float* src[4]; };

__global__ __launch_bounds__(256)
void split_w(WSplit ws, __half* __restrict__ hBase, int n4)
{
    const int w = blockIdx.y;
    const float* src = ws.src[w];
    __half* hi = hBase + (size_t)w * H_ * H_;
    int i = blockIdx.x * blockDim.x + threadIdx.x;
    if (i >= n4) return;
    float4 v = reinterpret_cast<const float4*>(src)[i];
    uint2 hu;
    hu.x = f16x2_rn(v.y * WSC, v.x * WSC);
    hu.y = f16x2_rn(v.w * WSC, v.z * WSC);
    reinterpret_cast<uint2*>(hi)[i] = hu;
}

// ---------------------------------------------------------------------------
// fp16 single-pass GEMM: C = (A @ (32W)^T)/32 + bias, then *scale.
// MODE 1: fused QKV (blockIdx.z), fp16 scatter [B*NH,S,HD].
// MODE 0: O-projection, fp32 out [M,H].
// ---------------------------------------------------------------------------
constexpr int RPB = 40;
constexpr int TB  = 128 * RPB * 2;      // 10240
constexpr int O_AH = 0, O_WH = TB;
constexpr int GBUF = 2 * TB;            // 20480
constexpr int GEMM_SMEM = 2 * GBUF;     // 40960

struct G3 {
    const float* bias[3];
    __half* out16[3];
    float scale[3];
};

template <int MODE>
__global__ __launch_bounds__(256)
void gemm1(const __half* __restrict__ Ah, const __half* __restrict__ WhB,
           G3 g, float* __restrict__ Cf)
{
    extern __shared__ char smem[];
    const uint32_t sb = smem_u32(smem);
    const int tid = threadIdx.x, wid = tid >> 5, lane = tid & 31;
    const int z = (MODE == 1) ? blockIdx.z : 0;
    const int m0 = blockIdx.y * 128, n0 = blockIdx.x * 128;
    const int wm = (wid & 1) * 64, wn = (wid >> 1) * 32;
    const __half* Wh = WhB + (size_t)z * H_ * H_;

    float acc[4][4][4];
    #pragma unroll
    for (int mi = 0; mi < 4; mi++)
        #pragma unroll
        for (int ni = 0; ni < 4; ni++)
            #pragma unroll
            for (int r = 0; r < 4; r++) acc[mi][ni][r] = 0.f;

    auto issue = [&](int c) {
        const int k0 = c * 32;
        const uint32_t bs = sb + (c & 1) * GBUF;
        #pragma unroll
        for (int t = 0; t < 2; t++) {
            int u = tid + t * 256;
            int row = u >> 2, seg = u & 3;
            uint32_t d = (row * RPB + seg * 8) * 2;
            cp_async16(bs + O_AH + d, Ah + (size_t)(m0 + row) * H_ + k0 + seg * 8);
            cp_async16(bs + O_WH + d, Wh + (size_t)(n0 + row) * H_ + k0 + seg * 8);
        }
        CP_COMMIT();
    };

    issue(0);
    constexpr int NCH = H_ / 32;

    for (int c = 0; c < NCH; c++) {
        if (c + 1 < NCH) { issue(c + 1); CP_WAIT(1); }
        else             { CP_WAIT(0); }
        __syncthreads();
        const uint32_t bs = sb + (c & 1) * GBUF;

        #pragma unroll
        for (int ks = 0; ks < 2; ks++) {
            const int l = lane & 15;
            uint32_t af[4][4], bh[4][2];
            #pragma unroll
            for (int mi = 0; mi < 4; mi++)
                ldmatrix_x4(af[mi], bs + O_AH +
                    ((wm + mi * 16 + l) * RPB + ks * 16 + (lane >> 4) * 8) * 2);
            #pragma unroll
            for (int ni = 0; ni < 4; ni++)
                ldmatrix_x2(bh[ni], bs + O_WH +
                    ((wn + ni * 8 + (l & 7)) * RPB + ks * 16 + (l >> 3) * 8) * 2);
            #pragma unroll
            for (int mi = 0; mi < 4; mi++)
                #pragma unroll
                for (int ni = 0; ni < 4; ni++)
                    mma_f16(acc[mi][ni], af[mi], bh[ni]);
        }
        __syncthreads();
    }

    const float scale = g.scale[z];
    const float* bias = g.bias[z];
    const int frow = lane >> 2, fcol = (lane & 3) * 2;
    #pragma unroll
    for (int mi = 0; mi < 4; mi++) {
        #pragma unroll
        for (int ni = 0; ni < 4; ni++) {
            const int n = n0 + wn + ni * 8 + fcol;
            const float b0 = __ldg(&bias[n]);
            const float b1 = __ldg(&bias[n + 1]);
            #pragma unroll
            for (int half = 0; half < 2; half++) {
                const int m = m0 + wm + mi * 16 + frow + half * 8;
                float vx = (acc[mi][ni][half * 2 + 0] * INV_WSC + b0) * scale;
                float vy = (acc[mi][ni][half * 2 + 1] * INV_WSC + b1) * scale;
                if (MODE == 0) {
                    float2 val{vx, vy};
                    *reinterpret_cast<float2*>(&Cf[(size_t)m * H_ + n]) = val;
                } else {
                    const int b = m >> 11, s = m & 2047;
                    const int h = n >> 6, hd = n & 63;
                    size_t idx = (((size_t)(b * NH_ + h)) * S_ + s) * HD_ + hd;
                    reinterpret_cast<uint32_t*>(g.out16[z])[idx >> 1] =
                        f16x2_rn(vy, vx);
                }
            }
        }
    }
}

// ---------------------------------------------------------------------------
// Flash attention, pure fp16 MMAs (QK 1 pass, PV 1 pass), base-2 softmax.
// KV buffer = 2 tiles (k, v). Q overlaid on buffer 1. 3 CTAs/SM.
// ---------------------------------------------------------------------------
constexpr int RP = 72, TSZ = 64 * RP * 2;   // 9216 B/tile
constexpr int KVBUF = 2 * TSZ;              // 18432
constexpr int ATTN_SMEM = 2 * KVBUF;        // 36864

__global__ __launch_bounds__(128, 3)
void attn_mma(const __half* __restrict__ q16, const __half* __restrict__ k16,
              const __half* __restrict__ v16, __half* __restrict__ aout)
{
    extern __shared__ char smem[];
    const uint32_t sb = smem_u32(smem);
    const int tid = threadIdx.x, wid = tid >> 5, lane = tid & 31;
    const int qt = 31 - blockIdx.x;
    const int bh = blockIdx.y;
    const int q0 = qt * 64;
    const size_t boff = (size_t)bh * S_ * HD_;
    const int wm = wid * 16;

    auto cp_tile = [&](uint32_t dst, const __half* src) {
        #pragma unroll
        for (int t = 0; t < 4; t++) {
            int u = tid + t * 128, r = u >> 3, ch = u & 7;
            cp_async16(dst + (r * RP + ch * 8) * 2, src + (size_t)r * HD_ + ch * 8);
        }
    };
    const uint32_t qoff = sb + KVBUF;     // Q overlays buffer 1
    cp_tile(qoff, q16 + boff + (size_t)q0 * HD_);
    CP_COMMIT();
    auto issue = [&](int kt) {
        uint32_t kb = sb + (kt & 1) * KVBUF;
        const size_t o = boff + (size_t)kt * 64 * HD_;
        cp_tile(kb, k16 + o);
        cp_tile(kb + TSZ, v16 + o);
        CP_COMMIT();
    };
    issue(0);
    CP_WAIT(1);        // Q complete
    __syncthreads();

    uint32_t qh[4][4];
    #pragma unroll
    for (int ks = 0; ks < 4; ks++) {
        uint32_t a = qoff + ((wm + (lane & 15)) * RP + ks * 16 + (lane >> 4) * 8) * 2;
        ldmatrix_x4(qh[ks], a);
    }
    __syncthreads();   // all warps done with Q before issue(1) overwrites it

    float o[8][4];
    #pragma unroll
    for (int j = 0; j < 8; j++)
        #pragma unroll
        for (int r = 0; r < 4; r++) o[j][r] = 0.f;
    float m_i[2] = {-1e30f, -1e30f}, l_i[2] = {0.f, 0.f};

    for (int kt = 0; kt <= qt; kt++) {
        if (kt < qt) { issue(kt + 1); CP_WAIT(1); }
        else         { CP_WAIT(0); }
        __syncthreads();
        const uint32_t kb = sb + (kt & 1) * KVBUF;

        float s[8][4];
        #pragma unroll
        for (int j = 0; j < 8; j++)
            #pragma unroll
            for (int r = 0; r < 4; r++) s[j][r] = 0.f;

        #pragma unroll
        for (int ks = 0; ks < 4; ks++) {
            #pragma unroll
            for (int j = 0; j < 8; j++) {
                uint32_t bh2[2];
                int l = lane & 15;
                uint32_t ka = kb + ((8 * j + (l & 7)) * RP + ks * 16 + (l >> 3) * 8) * 2;
                ldmatrix_x2(bh2, ka);
                mma_f16(s[j], qh[ks], bh2);
            }
        }

        if (kt == qt) {
            const int r0 = wm + (lane >> 2);
            #pragma unroll
            for (int j = 0; j < 8; j++) {
                const int kc = 8 * j + 2 * (lane & 3);
                if (kc     > r0)     s[j][0] = -1e30f;
                if (kc + 1 > r0)     s[j][1] = -1e30f;
                if (kc     > r0 + 8) s[j][2] = -1e30f;
                if (kc + 1 > r0 + 8) s[j][3] = -1e30f;
            }
        }

        float mx0 = -1e30f, mx1 = -1e30f;
        #pragma unroll
        for (int j = 0; j < 8; j++) {
            mx0 = fmaxf(mx0, fmaxf(s[j][0], s[j][1]));
            mx1 = fmaxf(mx1, fmaxf(s[j][2], s[j][3]));
        }
        mx0 = fmaxf(mx0, __shfl_xor_sync(~0u, mx0, 1));
        mx0 = fmaxf(mx0, __shfl_xor_sync(~0u, mx0, 2));
        mx1 = fmaxf(mx1, __shfl_xor_sync(~0u, mx1, 1));
        mx1 = fmaxf(mx1, __shfl_xor_sync(~0u, mx1, 2));
        const float nm0 = fmaxf(m_i[0], mx0), nm1 = fmaxf(m_i[1], mx1);
        const float c0 = ex2f(m_i[0] - nm0), c1 = ex2f(m_i[1] - nm1);
        m_i[0] = nm0; m_i[1] = nm1;

        float rs0 = 0.f, rs1 = 0.f;
        #pragma unroll
        for (int j = 0; j < 8; j++) {
            s[j][0] = ex2f(s[j][0] - nm0);
            s[j][1] = ex2f(s[j][1] - nm0);
            s[j][2] = ex2f(s[j][2] - nm1);
            s[j][3] = ex2f(s[j][3] - nm1);
            rs0 += s[j][0] + s[j][1];
            rs1 += s[j][2] + s[j][3];
        }
        rs0 += __shfl_xor_sync(~0u, rs0, 1);
        rs0 += __shfl_xor_sync(~0u, rs0, 2);
        rs1 += __shfl_xor_sync(~0u, rs1, 1);
        rs1 += __shfl_xor_sync(~0u, rs1, 2);
        l_i[0] = l_i[0] * c0 + rs0;
        l_i[1] = l_i[1] * c1 + rs1;
        #pragma unroll
        for (int j = 0; j < 8; j++) {
            o[j][0] *= c0; o[j][1] *= c0;
            o[j][2] *= c1; o[j][3] *= c1;
        }

        uint32_t ph[4][4];
        #pragma unroll
        for (int k2 = 0; k2 < 4; k2++) {
            #pragma unroll
            for (int half = 0; half < 2; half++) {
                const int j = 2 * k2 + half;
                ph[k2][half * 2 + 0] = f16x2_rn(s[j][1], s[j][0]);
                ph[k2][half * 2 + 1] = f16x2_rn(s[j][3], s[j][2]);
            }
        }

        const uint32_t vb = kb + TSZ;
        #pragma unroll
        for (int k2 = 0; k2 < 4; k2++) {
            #pragma unroll
            for (int j = 0; j < 8; j++) {
                uint32_t vh2[2];
                uint32_t va = vb + ((k2 * 16 + (lane & 15)) * RP + 8 * j) * 2;
                ldmatrix_x2_trans(vh2, va);
                mma_f16(o[j], ph[k2], vh2);
            }
        }
        __syncthreads();
    }

    const float inv0 = 1.f / l_i[0], inv1 = 1.f / l_i[1];
    const int b = bh >> 4, h = bh & 15;
    const int r0 = q0 + wm + (lane >> 2);
    const size_t base0 = ((size_t)(b * S_) + r0) * H_ + h * 64;
    const size_t base1 = base0 + (size_t)8 * H_;
    #pragma unroll
    for (int j = 0; j < 8; j++) {
        const int c = 8 * j + 2 * (lane & 3);
        reinterpret_cast<uint32_t*>(aout)[(base0 + c) >> 1] =
            f16x2_rn(o[j][1] * inv0, o[j][0] * inv0);
        reinterpret_cast<uint32_t*>(aout)[(base1 + c) >> 1] =
            f16x2_rn(o[j][3] * inv1, o[j][2] * inv1);
    }
}

// ---------------------------------------------------------------------------
extern "C" void kernel_launch(void* const* d_in, const int* in_sizes, int n_in,
                              void* d_out, int out_size)
{
    const float* x  = (const float*)d_in[0];
    const float* Wq = (const float*)d_in[1];
    const float* bq = (const float*)d_in[2];
    const float* Wk = (const float*)d_in[3];
    const float* bk = (const float*)d_in[4];
    const float* Wv = (const float*)d_in[5];
    const float* bv = (const float*)d_in[6];
    const float* Wo = (const float*)d_in[7];
    const float* bo = (const float*)d_in[8];
    float* out = (float*)d_out;

    __half *xh, *wh, *ah, *q16, *k16, *v16;
    cudaGetSymbolAddress((void**)&xh, g_xh);
    cudaGetSymbolAddress((void**)&wh, g_wh);
    cudaGetSymbolAddress((void**)&ah, g_ah);
    cudaGetSymbolAddress((void**)&q16, g_q16);
    cudaGetSymbolAddress((void**)&k16, g_k16);
    cudaGetSymbolAddress((void**)&v16, g_v16);

    cudaFuncSetAttribute(gemm1<0>, cudaFuncAttributeMaxDynamicSharedMemorySize, GEMM_SMEM);
    cudaFuncSetAttribute(gemm1<1>, cudaFuncAttributeMaxDynamicSharedMemorySize, GEMM_SMEM);
    cudaFuncSetAttribute(attn_mma, cudaFuncAttributeMaxDynamicSharedMemorySize, ATTN_SMEM);

    const size_t WN = (size_t)H_ * H_;

    {
        int n4 = (M_ * H_) / 4;
        split_x<<<(n4 + 255) / 256, 256>>>(x, xh, n4);
        WSplit ws;
        ws.src[0] = Wq; ws.src[1] = Wk; ws.src[2] = Wv; ws.src[3] = Wo;
        int w4 = (H_ * H_) / 4;
        dim3 wg((w4 + 255) / 256, 4);
        split_w<<<wg, 256>>>(ws, wh, w4);
    }

    G3 g;
    g.bias[0] = bq;  g.bias[1] = bk;  g.bias[2] = bv;
    g.out16[0] = q16; g.out16[1] = k16; g.out16[2] = v16;
    g.scale[0] = SCALE_Q; g.scale[1] = 1.0f; g.scale[2] = 1.0f;
    dim3 gq(H_ / 128, M_ / 128, 3);
    gemm1<1><<<gq, 256, GEMM_SMEM>>>(xh, wh, g, nullptr);

    dim3 ag(S_ / 64, B_ * NH_);
    attn_mma<<<ag, 128, ATTN_SMEM>>>(q16, k16, v16, ah);

    G3 go;
    go.bias[0] = bo; go.bias[1] = bo; go.bias[2] = bo;
    go.out16[0] = nullptr; go.out16[1] = nullptr; go.out16[2] = nullptr;
    go.scale[0] = 1.0f; go.scale[1] = 1.0f; go.scale[2] = 1.0f;
    dim3 gg(H_ / 128, M_ / 128, 1);
    gemm1<0><<<gg, 256, GEMM_SMEM>>>(ah, wh + 3 * WN, go, out);
}

// round 13
// speedup vs baseline: 5.0952x; 1.0210x over previous
#include <cuda_runtime.h>
#include <cuda_fp16.h>
#include <cstdint>
#include <cstddef>

constexpr int B_ = 4, S_ = 2048, H_ = 1024, NH_ = 16, HD_ = 64;
constexpr int M_ = B_ * S_;
constexpr float SCALE_Q = 0.18033688011112042f;  // 0.125 * log2(e)
constexpr float WSC = 32.0f, INV_WSC = 1.0f / 32.0f;

// Scratch
__device__ __half g_xh[(size_t)M_ * H_];
__device__ __half g_wh[4 * (size_t)H_ * H_];
__device__ __half g_q16[(size_t)M_ * H_];
__device__ __half g_k16[(size_t)M_ * H_];
__device__ __half g_v16[(size_t)M_ * H_];
__device__ __half g_ah[(size_t)M_ * H_];

__device__ __forceinline__ uint32_t smem_u32(const void* p) {
    uint32_t a;
    asm("{ .reg .u64 t; cvta.to.shared.u64 t, %1; cvt.u32.u64 %0, t; }"
        : "=r"(a) : "l"(p));
    return a;
}
__device__ __forceinline__ void cp_async16(uint32_t dst, const void* src) {
    asm volatile("cp.async.cg.shared.global [%0], [%1], 16;"
                 :: "r"(dst), "l"(src) : "memory");
}
#define CP_COMMIT() asm volatile("cp.async.commit_group;" ::: "memory")
#define CP_WAIT(n)  asm volatile("cp.async.wait_group %0;" :: "n"(n) : "memory")

__device__ __forceinline__ void ldmatrix_x4(uint32_t* r, uint32_t a) {
    asm volatile("ldmatrix.sync.aligned.m8n8.x4.shared.b16 {%0,%1,%2,%3}, [%4];"
                 : "=r"(r[0]), "=r"(r[1]), "=r"(r[2]), "=r"(r[3]) : "r"(a));
}
__device__ __forceinline__ void ldmatrix_x4_trans(uint32_t* r, uint32_t a) {
    asm volatile("ldmatrix.sync.aligned.m8n8.x4.trans.shared.b16 {%0,%1,%2,%3}, [%4];"
                 : "=r"(r[0]), "=r"(r[1]), "=r"(r[2]), "=r"(r[3]) : "r"(a));
}
__device__ __forceinline__ void mma_f16(float* c, const uint32_t* a,
                                        const uint32_t* b) {
    asm volatile(
        "mma.sync.aligned.m16n8k16.row.col.f32.f16.f16.f32 "
        "{%0,%1,%2,%3}, {%4,%5,%6,%7}, {%8,%9}, {%0,%1,%2,%3};"
        : "+f"(c[0]), "+f"(c[1]), "+f"(c[2]), "+f"(c[3])
        : "r"(a[0]), "r"(a[1]), "r"(a[2]), "r"(a[3]), "r"(b[0]), "r"(b[1]));
}
__device__ __forceinline__ float ex2f(float x) {
    float y; asm("ex2.approx.ftz.f32 %0, %1;" : "=f"(y) : "f"(x)); return y;
}
__device__ __forceinline__ uint32_t f16x2_rn(float h, float l) {
    uint32_t d;
    asm("cvt.rn.f16x2.f32 %0, %1, %2;" : "=r"(d) : "f"(h), "f"(l));
    return d;
}

// ---------------------------------------------------------------------------
// Splits
// ---------------------------------------------------------------------------
__global__ __launch_bounds__(256)
void split_x(const float* __restrict__ src, __half* __restrict__ h, int n4)
{
    int i = blockIdx.x * blockDim.x + threadIdx.x;
    if (i >= n4) return;
    float4 v = reinterpret_cast<const float4*>(src)[i];
    uint2 hu;
    hu.x = f16x2_rn(v.y, v.x);
    hu.y = f16x2_rn(v.w, v.z);
    reinterpret_cast<uint2*>(h)[i] = hu;
}

struct WSplit { const float* src[4]; };

__global__ __launch_bounds__(256)
void split_w(WSplit ws, __half* __restrict__ hBase, int n4)
{
    const int w = blockIdx.y;
    const float* src = ws.src[w];
    __half* hi = hBase + (size_t)w * H_ * H_;
    int i = blockIdx.x * blockDim.x + threadIdx.x;
    if (i >= n4) return;
    float4 v = reinterpret_cast<const float4*>(src)[i];
    uint2 hu;
    hu.x = f16x2_rn(v.y * WSC, v.x * WSC);
    hu.y = f16x2_rn(v.w * WSC, v.z * WSC);
    reinterpret_cast<uint2*>(hi)[i] = hu;
}

// ---------------------------------------------------------------------------
// fp16 single-pass GEMM: C = (A @ (32W)^T)/32 + bias, then *scale.
// W-fragments now loaded with x4 ldmatrix (2 per ks instead of 4 x2).
// ---------------------------------------------------------------------------
constexpr int RPB = 40;
constexpr int TB  = 128 * RPB * 2;
constexpr int O_AH = 0, O_WH = TB;
constexpr int GBUF = 2 * TB;
constexpr int GEMM_SMEM = 2 * GBUF;

struct G3 {
    const float* bias[3];
    __half* out16[3];
    float scale[3];
};

template <int MODE>
__global__ __launch_bounds__(256)
void gemm1(const __half* __restrict__ Ah, const __half* __restrict__ WhB,
           G3 g, float* __restrict__ Cf)
{
    extern __shared__ char smem[];
    const uint32_t sb = smem_u32(smem);
    const int tid = threadIdx.x, wid = tid >> 5, lane = tid & 31;
    const int z = (MODE == 1) ? blockIdx.z : 0;
    const int m0 = blockIdx.y * 128, n0 = blockIdx.x * 128;
    const int wm = (wid & 1) * 64, wn = (wid >> 1) * 32;
    const __half* Wh = WhB + (size_t)z * H_ * H_;

    float acc[4][4][4];
    #pragma unroll
    for (int mi = 0; mi < 4; mi++)
        #pragma unroll
        for (int ni = 0; ni < 4; ni++)
            #pragma unroll
            for (int r = 0; r < 4; r++) acc[mi][ni][r] = 0.f;

    auto issue = [&](int c) {
        const int k0 = c * 32;
        const uint32_t bs = sb + (c & 1) * GBUF;
        #pragma unroll
        for (int t = 0; t < 2; t++) {
            int u = tid + t * 256;
            int row = u >> 2, seg = u & 3;
            uint32_t d = (row * RPB + seg * 8) * 2;
            cp_async16(bs + O_AH + d, Ah + (size_t)(m0 + row) * H_ + k0 + seg * 8);
            cp_async16(bs + O_WH + d, Wh + (size_t)(n0 + row) * H_ + k0 + seg * 8);
        }
        CP_COMMIT();
    };

    issue(0);
    constexpr int NCH = H_ / 32;

    for (int c = 0; c < NCH; c++) {
        if (c + 1 < NCH) { issue(c + 1); CP_WAIT(1); }
        else             { CP_WAIT(0); }
        __syncthreads();
        const uint32_t bs = sb + (c & 1) * GBUF;

        #pragma unroll
        for (int ks = 0; ks < 2; ks++) {
            const int l = lane & 15;
            uint32_t af[4][4], bh[4][2];
            #pragma unroll
            for (int mi = 0; mi < 4; mi++)
                ldmatrix_x4(af[mi], bs + O_AH +
                    ((wm + mi * 16 + l) * RPB + ks * 16 + (lane >> 4) * 8) * 2);
            #pragma unroll
            for (int n2 = 0; n2 < 2; n2++) {
                uint32_t bb[4];
                uint32_t addr = bs + O_WH +
                    ((wn + 8 * (2 * n2 + ((lane >> 4) & 1)) + (lane & 7)) * RPB +
                     ks * 16 + ((lane >> 3) & 1) * 8) * 2;
                ldmatrix_x4(bb, addr);
                bh[2 * n2][0] = bb[0]; bh[2 * n2][1] = bb[1];
                bh[2 * n2 + 1][0] = bb[2]; bh[2 * n2 + 1][1] = bb[3];
            }
            #pragma unroll
            for (int mi = 0; mi < 4; mi++)
                #pragma unroll
                for (int ni = 0; ni < 4; ni++)
                    mma_f16(acc[mi][ni], af[mi], bh[ni]);
        }
        __syncthreads();
    }

    const float scale = g.scale[z];
    const float* bias = g.bias[z];
    const int frow = lane >> 2, fcol = (lane & 3) * 2;
    #pragma unroll
    for (int mi = 0; mi < 4; mi++) {
        #pragma unroll
        for (int ni = 0; ni < 4; ni++) {
            const int n = n0 + wn + ni * 8 + fcol;
            const float b0 = __ldg(&bias[n]);
            const float b1 = __ldg(&bias[n + 1]);
            #pragma unroll
            for (int half = 0; half < 2; half++) {
                const int m = m0 + wm + mi * 16 + frow + half * 8;
                float vx = (acc[mi][ni][half * 2 + 0] * INV_WSC + b0) * scale;
                float vy = (acc[mi][ni][half * 2 + 1] * INV_WSC + b1) * scale;
                if (MODE == 0) {
                    float2 val{vx, vy};
                    *reinterpret_cast<float2*>(&Cf[(size_t)m * H_ + n]) = val;
                } else {
                    const int b = m >> 11, s = m & 2047;
                    const int h = n >> 6, hd = n & 63;
                    size_t idx = (((size_t)(b * NH_ + h)) * S_ + s) * HD_ + hd;
                    reinterpret_cast<uint32_t*>(g.out16[z])[idx >> 1] =
                        f16x2_rn(vy, vx);
                }
            }
        }
    }
}

// ---------------------------------------------------------------------------
// Flash attention, fp16 1-pass QK + 1-pass PV, x4-batched LDSM.
// ---------------------------------------------------------------------------
constexpr int RP = 72, TSZ = 64 * RP * 2;
constexpr int KVBUF = 2 * TSZ;
constexpr int ATTN_SMEM = 2 * KVBUF;    // 36864

__global__ __launch_bounds__(128, 3)
void attn_mma(const __half* __restrict__ q16, const __half* __restrict__ k16,
              const __half* __restrict__ v16, __half* __restrict__ aout)
{
    extern __shared__ char smem[];
    const uint32_t sb = smem_u32(smem);
    const int tid = threadIdx.x, wid = tid >> 5, lane = tid & 31;
    const int qt = 31 - blockIdx.x;
    const int bh = blockIdx.y;
    const int q0 = qt * 64;
    const size_t boff = (size_t)bh * S_ * HD_;
    const int wm = wid * 16;

    auto cp_tile = [&](uint32_t dst, const __half* src) {
        #pragma unroll
        for (int t = 0; t < 4; t++) {
            int u = tid + t * 128, r = u >> 3, ch = u & 7;
            cp_async16(dst + (r * RP + ch * 8) * 2, src + (size_t)r * HD_ + ch * 8);
        }
    };
    const uint32_t qoff = sb + KVBUF;
    cp_tile(qoff, q16 + boff + (size_t)q0 * HD_);
    CP_COMMIT();
    auto issue = [&](int kt) {
        uint32_t kb = sb + (kt & 1) * KVBUF;
        const size_t o = boff + (size_t)kt * 64 * HD_;
        cp_tile(kb, k16 + o);
        cp_tile(kb + TSZ, v16 + o);
        CP_COMMIT();
    };
    issue(0);
    CP_WAIT(1);
    __syncthreads();

    uint32_t qh[4][4];
    #pragma unroll
    for (int ks = 0; ks < 4; ks++) {
        uint32_t a = qoff + ((wm + (lane & 15)) * RP + ks * 16 + (lane >> 4) * 8) * 2;
        ldmatrix_x4(qh[ks], a);
    }
    __syncthreads();

    float o[8][4];
    #pragma unroll
    for (int j = 0; j < 8; j++)
        #pragma unroll
        for (int r = 0; r < 4; r++) o[j][r] = 0.f;
    float m_i[2] = {-1e30f, -1e30f}, l_i[2] = {0.f, 0.f};

    for (int kt = 0; kt <= qt; kt++) {
        if (kt < qt) { issue(kt + 1); CP_WAIT(1); }
        else         { CP_WAIT(0); }
        __syncthreads();
        const uint32_t kb = sb + (kt & 1) * KVBUF;

        float s[8][4];
        #pragma unroll
        for (int j = 0; j < 8; j++)
            #pragma unroll
            for (int r = 0; r < 4; r++) s[j][r] = 0.f;

        // QK: x4 LDSM loads two n-tiles at once (lanes 16-31 -> second tile)
        #pragma unroll
        for (int ks = 0; ks < 4; ks++) {
            #pragma unroll
            for (int j2 = 0; j2 < 4; j2++) {
                uint32_t bb[4];
                uint32_t ka = kb +
                    ((8 * (2 * j2 + ((lane >> 4) & 1)) + (lane & 7)) * RP +
                     ks * 16 + ((lane >> 3) & 1) * 8) * 2;
                ldmatrix_x4(bb, ka);
                mma_f16(s[2 * j2],     qh[ks], bb);
                mma_f16(s[2 * j2 + 1], qh[ks], bb + 2);
            }
        }

        if (kt == qt) {
            const int r0 = wm + (lane >> 2);
            #pragma unroll
            for (int j = 0; j < 8; j++) {
                const int kc = 8 * j + 2 * (lane & 3);
                if (kc     > r0)     s[j][0] = -1e30f;
                if (kc + 1 > r0)     s[j][1] = -1e30f;
                if (kc     > r0 + 8) s[j][2] = -1e30f;
                if (kc + 1 > r0 + 8) s[j][3] = -1e30f;
            }
        }

        float mx0 = -1e30f, mx1 = -1e30f;
        #pragma unroll
        for (int j = 0; j < 8; j++) {
            mx0 = fmaxf(mx0, fmaxf(s[j][0], s[j][1]));
            mx1 = fmaxf(mx1, fmaxf(s[j][2], s[j][3]));
        }
        mx0 = fmaxf(mx0, __shfl_xor_sync(~0u, mx0, 1));
        mx0 = fmaxf(mx0, __shfl_xor_sync(~0u, mx0, 2));
        mx1 = fmaxf(mx1, __shfl_xor_sync(~0u, mx1, 1));
        mx1 = fmaxf(mx1, __shfl_xor_sync(~0u, mx1, 2));
        const float nm0 = fmaxf(m_i[0], mx0), nm1 = fmaxf(m_i[1], mx1);
        const float c0 = ex2f(m_i[0] - nm0), c1 = ex2f(m_i[1] - nm1);
        m_i[0] = nm0; m_i[1] = nm1;

        float rs0 = 0.f, rs1 = 0.f;
        #pragma unroll
        for (int j = 0; j < 8; j++) {
            s[j][0] = ex2f(s[j][0] - nm0);
            s[j][1] = ex2f(s[j][1] - nm0);
            s[j][2] = ex2f(s[j][2] - nm1);
            s[j][3] = ex2f(s[j][3] - nm1);
            rs0 += s[j][0] + s[j][1];
            rs1 += s[j][2] + s[j][3];
        }
        rs0 += __shfl_xor_sync(~0u, rs0, 1);
        rs0 += __shfl_xor_sync(~0u, rs0, 2);
        rs1 += __shfl_xor_sync(~0u, rs1, 1);
        rs1 += __shfl_xor_sync(~0u, rs1, 2);
        l_i[0] = l_i[0] * c0 + rs0;
        l_i[1] = l_i[1] * c1 + rs1;
        #pragma unroll
        for (int j = 0; j < 8; j++) {
            o[j][0] *= c0; o[j][1] *= c0;
            o[j][2] *= c1; o[j][3] *= c1;
        }

        uint32_t ph[4][4];
        #pragma unroll
        for (int k2 = 0; k2 < 4; k2++) {
            #pragma unroll
            for (int half = 0; half < 2; half++) {
                const int j = 2 * k2 + half;
                ph[k2][half * 2 + 0] = f16x2_rn(s[j][1], s[j][0]);
                ph[k2][half * 2 + 1] = f16x2_rn(s[j][3], s[j][2]);
            }
        }

        // PV: x4 trans LDSM loads two n-tiles (lanes 16-31 -> cols +8)
        const uint32_t vb = kb + TSZ;
        #pragma unroll
        for (int k2 = 0; k2 < 4; k2++) {
            #pragma unroll
            for (int j2 = 0; j2 < 4; j2++) {
                uint32_t vv[4];
                uint32_t va = vb +
                    ((k2 * 16 + (lane & 15)) * RP + 16 * j2 + (lane >> 4) * 8) * 2;
                ldmatrix_x4_trans(vv, va);
                mma_f16(o[2 * j2],     ph[k2], vv);
                mma_f16(o[2 * j2 + 1], ph[k2], vv + 2);
            }
        }
        __syncthreads();
    }

    const float inv0 = 1.f / l_i[0], inv1 = 1.f / l_i[1];
    const int b = bh >> 4, h = bh & 15;
    const int r0 = q0 + wm + (lane >> 2);
    const size_t base0 = ((size_t)(b * S_) + r0) * H_ + h * 64;
    const size_t base1 = base0 + (size_t)8 * H_;
    #pragma unroll
    for (int j = 0; j < 8; j++) {
        const int c = 8 * j + 2 * (lane & 3);
        reinterpret_cast<uint32_t*>(aout)[(base0 + c) >> 1] =
            f16x2_rn(o[j][1] * inv0, o[j][0] * inv0);
        reinterpret_cast<uint32_t*>(aout)[(base1 + c) >> 1] =
            f16x2_rn(o[j][3] * inv1, o[j][2] * inv1);
    }
}

// ---------------------------------------------------------------------------
extern "C" void kernel_launch(void* const* d_in, const int* in_sizes, int n_in,
                              void* d_out, int out_size)
{
    const float* x  = (const float*)d_in[0];
    const float* Wq = (const float*)d_in[1];
    const float* bq = (const float*)d_in[2];
    const float* Wk = (const float*)d_in[3];
    const float* bk = (const float*)d_in[4];
    const float* Wv = (const float*)d_in[5];
    const float* bv = (const float*)d_in[6];
    const float* Wo = (const float*)d_in[7];
    const float* bo = (const float*)d_in[8];
    float* out = (float*)d_out;

    __half *xh, *wh, *ah, *q16, *k16, *v16;
    cudaGetSymbolAddress((void**)&xh, g_xh);
    cudaGetSymbolAddress((void**)&wh, g_wh);
    cudaGetSymbolAddress((void**)&ah, g_ah);
    cudaGetSymbolAddress((void**)&q16, g_q16);
    cudaGetSymbolAddress((void**)&k16, g_k16);
    cudaGetSymbolAddress((void**)&v16, g_v16);

    cudaFuncSetAttribute(gemm1<0>, cudaFuncAttributeMaxDynamicSharedMemorySize, GEMM_SMEM);
    cudaFuncSetAttribute(gemm1<1>, cudaFuncAttributeMaxDynamicSharedMemorySize, GEMM_SMEM);
    cudaFuncSetAttribute(attn_mma, cudaFuncAttributeMaxDynamicSharedMemorySize, ATTN_SMEM);

    const size_t WN = (size_t)H_ * H_;

    {
        int n4 = (M_ * H_) / 4;
        split_x<<<(n4 + 255) / 256, 256>>>(x, xh, n4);
        WSplit ws;
        ws.src[0] = Wq; ws.src[1] = Wk; ws.src[2] = Wv; ws.src[3] = Wo;
        int w4 = (H_ * H_) / 4;
        dim3 wg((w4 + 255) / 256, 4);
        split_w<<<wg, 256>>>(ws, wh, w4);
    }

    G3 g;
    g.bias[0] = bq;  g.bias[1] = bk;  g.bias[2] = bv;
    g.out16[0] = q16; g.out16[1] = k16; g.out16[2] = v16;
    g.scale[0] = SCALE_Q; g.scale[1] = 1.0f; g.scale[2] = 1.0f;
    dim3 gq(H_ / 128, M_ / 128, 3);
    gemm1<1><<<gq, 256, GEMM_SMEM>>>(xh, wh, g, nullptr);

    dim3 ag(S_ / 64, B_ * NH_);
    attn_mma<<<ag, 128, ATTN_SMEM>>>(q16, k16, v16, ah);

    G3 go;
    go.bias[0] = bo; go.bias[1] = bo; go.bias[2] = bo;
    go.out16[0] = nullptr; go.out16[1] = nullptr; go.out16[2] = nullptr;
    go.scale[0] = 1.0f; go.scale[1] = 1.0f; go.scale[2] = 1.0f;
    dim3 gg(H_ / 128, M_ / 128, 1);
    gemm1<0><<<gg, 256, GEMM_SMEM>>>(ah, wh + 3 * WN, go, out);
}